// round 1
// baseline (speedup 1.0000x reference)
#include <cuda_runtime.h>
#include <math_constants.h>

// Problem-scale constants (from reference: N=40000 nodes, E=320000 edges)
#define NN 40000
#define NE 320000

// ---------------- scratch (device globals; no allocation allowed) ----------------
__device__ float fG[NN * 32];        // layer-normed features, (N, 8, 4)
__device__ float scoresG[NE * 4];    // leakyrelu'd attention logits, (E, 4)
__device__ float vG[NE * 32];        // per-edge v, (E, 8, 4) flattened
__device__ float smaxG[NN * 4];      // segment max per (dst, head)
__device__ float denG[NN * 4];       // softmax denominator
__device__ float numG[NN * 32];      // softmax-weighted v accumulator

__device__ __forceinline__ void atomicMaxF(float* a, float v) {
    if (v == 0.0f) v = 0.0f;  // canonicalize -0 -> +0
    if (v >= 0.0f) atomicMax((int*)a, __float_as_int(v));
    else           atomicMin((unsigned int*)a, __float_as_uint(v));
}

// ---------------- init scratch ----------------
__global__ void init_kernel(int N) {
    int i = blockIdx.x * blockDim.x + threadIdx.x;
    if (i < N * 4) { smaxG[i] = -CUDART_INF_F; denG[i] = 0.0f; }
    if (i < N * 32) numG[i] = 0.0f;
}

// ---------------- node-wise equivariant layer norm ----------------
// norms (N,8,2) viewed flat as (N,2,8); LN over last dim; relu; scale features.
__global__ void node_ln_kernel(const float* __restrict__ features,
                               const float* __restrict__ ln_w,
                               const float* __restrict__ ln_b, int N) {
    int n = blockIdx.x * blockDim.x + threadIdx.x;
    if (n >= N) return;
    float f[32];
    const float4* fp = (const float4*)(features + (size_t)n * 32);
#pragma unroll
    for (int q = 0; q < 8; q++) {
        float4 v = fp[q];
        f[q * 4 + 0] = v.x; f[q * 4 + 1] = v.y; f[q * 4 + 2] = v.z; f[q * 4 + 3] = v.w;
    }
    float nf[16];
#pragma unroll
    for (int m = 0; m < 8; m++) {
        nf[2 * m]     = sqrtf(f[m * 4] * f[m * 4]);
        nf[2 * m + 1] = sqrtf(f[m * 4 + 1] * f[m * 4 + 1] +
                              f[m * 4 + 2] * f[m * 4 + 2] +
                              f[m * 4 + 3] * f[m * 4 + 3]);
    }
    float ratio[16];
#pragma unroll
    for (int g = 0; g < 2; g++) {
        float mu = 0.0f;
#pragma unroll
        for (int b = 0; b < 8; b++) mu += nf[8 * g + b];
        mu *= 0.125f;
        float var = 0.0f;
#pragma unroll
        for (int b = 0; b < 8; b++) { float d = nf[8 * g + b] - mu; var += d * d; }
        var *= 0.125f;
        float rs = rsqrtf(var + 1e-5f);
#pragma unroll
        for (int b = 0; b < 8; b++) {
            float l = (nf[8 * g + b] - mu) * rs * ln_w[b] + ln_b[b];
            l = fmaxf(l, 0.0f);
            ratio[8 * g + b] = l / (nf[8 * g + b] + 1e-8f);
        }
    }
    float4* op = (float4*)(fG + (size_t)n * 32);
#pragma unroll
    for (int m = 0; m < 8; m++) {
        float4 v;
        v.x = f[m * 4 + 0] * ratio[2 * m];
        v.y = f[m * 4 + 1] * ratio[2 * m + 1];
        v.z = f[m * 4 + 2] * ratio[2 * m + 1];
        v.w = f[m * 4 + 3] * ratio[2 * m + 1];
        op[m] = v;
    }
}

// ---------------- fused per-edge kernel ----------------
// 32 edges / block, 256 threads. Dynamic smem layout (floats):
#define SM_W1    0      // [k][j] transposed, 32*64
#define SM_B1    2048   // 64
#define SM_B2    2112   // 768
#define SM_EF    2880   // [el][32]
#define SM_FU    3904   // [el][32]
#define SM_BAS   4928   // [el][64]
#define SM_H     6976   // [el][68]  (pad 68 for bank spread)
#define SM_TMP   9152   // [el][132] (32 j * 4 d, pad 132)
#define SM_CONV  13376  // [el][100] (24 i * 4 d, pad 100)
#define SM_TOTAL 16576

__global__ __launch_bounds__(256, 2)
void edge_kernel(const int* __restrict__ src, const int* __restrict__ dst,
                 const float* __restrict__ basis, const float* __restrict__ edge_feats,
                 const float* __restrict__ w1, const float* __restrict__ b1,
                 const float* __restrict__ w2, const float* __restrict__ b2,
                 int E) {
    extern __shared__ float sm[];
    int t = threadIdx.x;
    int e0 = blockIdx.x * 32;

    // stage w1 (transposed), b1, b2
    for (int idx = t; idx < 2048; idx += 256) {
        int j = idx >> 5, k = idx & 31;
        sm[SM_W1 + k * 64 + j] = w1[idx];
    }
    if (t < 64) sm[SM_B1 + t] = b1[t];
    for (int idx = t; idx < 768; idx += 256) sm[SM_B2 + idx] = b2[idx];

    int el = t >> 3, part = t & 7;
    int e = e0 + el;
    bool ein = e < E;
    int ec = ein ? e : (E - 1);

    // stage edge_feats, gathered features, basis
    {
        float4 v4 = ((const float4*)edge_feats)[(size_t)ec * 8 + part];
        *(float4*)&sm[SM_EF + el * 32 + part * 4] = v4;
        int s = src[ec];
        float4 f4 = ((const float4*)fG)[(size_t)s * 8 + part];
        *(float4*)&sm[SM_FU + el * 32 + part * 4] = f4;
        float4 bA = ((const float4*)basis)[(size_t)ec * 16 + part];
        float4 bB = ((const float4*)basis)[(size_t)ec * 16 + 8 + part];
        *(float4*)&sm[SM_BAS + el * 64 + part * 4] = bA;
        *(float4*)&sm[SM_BAS + el * 64 + 32 + part * 4] = bB;
    }
    __syncthreads();

    // h = relu(ef @ w1^T + b1): 8 outputs per thread
    {
        float efr[32];
#pragma unroll
        for (int k = 0; k < 32; k++) efr[k] = sm[SM_EF + el * 32 + k];
#pragma unroll
        for (int jj = 0; jj < 8; jj++) {
            int j = part + 8 * jj;
            float acc = sm[SM_B1 + j];
#pragma unroll
            for (int k = 0; k < 32; k++) acc += efr[k] * sm[SM_W1 + k * 64 + j];
            sm[SM_H + el * 68 + j] = fmaxf(acc, 0.0f);
        }
    }
    // tmp2[j][d] = sum_dd fU[m][dd]*basis[dd][p*4+d], j = m*4+p
#pragma unroll
    for (int jj = 0; jj < 4; jj++) {
        int j = part * 4 + jj;
        int m = j >> 2, p = j & 3;
        float o0 = 0.f, o1 = 0.f, o2 = 0.f, o3 = 0.f;
#pragma unroll
        for (int dd = 0; dd < 4; dd++) {
            float fv = sm[SM_FU + el * 32 + m * 4 + dd];
            o0 += fv * sm[SM_BAS + el * 64 + dd * 16 + p * 4 + 0];
            o1 += fv * sm[SM_BAS + el * 64 + dd * 16 + p * 4 + 1];
            o2 += fv * sm[SM_BAS + el * 64 + dd * 16 + p * 4 + 2];
            o3 += fv * sm[SM_BAS + el * 64 + dd * 16 + p * 4 + 3];
        }
        sm[SM_TMP + el * 132 + j * 4 + 0] = o0;
        sm[SM_TMP + el * 132 + j * 4 + 1] = o1;
        sm[SM_TMP + el * 132 + j * 4 + 2] = o2;
        sm[SM_TMP + el * 132 + j * 4 + 3] = o3;
    }
    __syncthreads();

    // Phase B: conv[e,i,d] = sum_j (b2[ij] + h.w2[ij,:]) * tmp2[e,j,d]
    // Thread: edge eb = t&31 (lane-distinct), i in {ig, ig+8, ig+16}.
    // w2 LDG.128 is warp-uniform -> broadcast, ~free vs the 4 FMAs it feeds.
    {
        int eb = t & 31;
        int ig = t >> 5;
        float4 hreg[16];
#pragma unroll
        for (int k4 = 0; k4 < 16; k4++)
            hreg[k4] = *(const float4*)&sm[SM_H + eb * 68 + k4 * 4];

#pragma unroll 1
        for (int i3 = 0; i3 < 3; i3++) {
            int i = ig + 8 * i3;
            float a0 = 0.f, a1 = 0.f, a2 = 0.f, a3 = 0.f;
            const float4* wbase = (const float4*)(w2 + (size_t)i * 32 * 64);
#pragma unroll 2
            for (int j = 0; j < 32; j++) {
                const float4* wrow = wbase + j * 16;
                float r0 = sm[SM_B2 + i * 32 + j], r1 = 0.f, r2 = 0.f, r3 = 0.f;
#pragma unroll
                for (int k4 = 0; k4 < 16; k4++) {
                    float4 wv = __ldg(wrow + k4);
                    float4 hv = hreg[k4];
                    r0 += wv.x * hv.x; r1 += wv.y * hv.y;
                    r2 += wv.z * hv.z; r3 += wv.w * hv.w;
                }
                float rw = (r0 + r1) + (r2 + r3);
                float4 tp = *(const float4*)&sm[SM_TMP + eb * 132 + j * 4];
                a0 += rw * tp.x; a1 += rw * tp.y; a2 += rw * tp.z; a3 += rw * tp.w;
            }
            sm[SM_CONV + eb * 100 + i * 4 + 0] = a0;
            sm[SM_CONV + eb * 100 + i * 4 + 1] = a1;
            sm[SM_CONV + eb * 100 + i * 4 + 2] = a2;
            sm[SM_CONV + eb * 100 + i * 4 + 3] = a3;
        }
    }
    __syncthreads();

    // Phase C: scores (k.q per head), leakyrelu, atomicMax; write v
    if (t < 128) {
        int eb2 = t & 31, h = t >> 5;
        float sc = 0.0f;
#pragma unroll
        for (int x = 0; x < 8; x++) {
            int m = 2 * h + (x >> 2), d = x & 3;
            sc += sm[SM_CONV + eb2 * 100 + m * 4 + d] *
                  sm[SM_CONV + eb2 * 100 + (8 + m) * 4 + d];
        }
        sc *= 0.17677669529663687f;          // 32^-0.5
        sc = sc >= 0.0f ? sc : 0.2f * sc;    // LeakyReLU(0.2)
        int ee = e0 + eb2;
        if (ee < E) {
            scoresG[ee * 4 + h] = sc;
            atomicMaxF(&smaxG[dst[ee] * 4 + h], sc);
        }
    }
    if (ein) {
        float4 vv = *(float4*)&sm[SM_CONV + el * 100 + 64 + part * 4];
        ((float4*)vG)[(size_t)e * 8 + part] = vv;
    }
}

// ---------------- softmax accumulate (pass 2 over edges) ----------------
__global__ void attn_kernel(const int* __restrict__ dst, int E) {
    int idx = blockIdx.x * blockDim.x + threadIdx.x;
    if (idx >= E * 4) return;
    int e = idx >> 2, h = idx & 3;
    int dn = dst[e];
    float ex = expf(scoresG[idx] - smaxG[dn * 4 + h]);
    atomicAdd(&denG[dn * 4 + h], ex);
    const float4* vp = (const float4*)(vG + (size_t)e * 32 + h * 8);
    float4 va = vp[0], vb = vp[1];
    float* np = numG + (size_t)dn * 32 + h * 8;
    atomicAdd(np + 0, ex * va.x);
    atomicAdd(np + 1, ex * va.y);
    atomicAdd(np + 2, ex * va.z);
    atomicAdd(np + 3, ex * va.w);
    atomicAdd(np + 4, ex * vb.x);
    atomicAdd(np + 5, ex * vb.y);
    atomicAdd(np + 6, ex * vb.z);
    atomicAdd(np + 7, ex * vb.w);
}

// ---------------- node output: divide + per-irrep projection ----------------
__global__ void out_kernel(const float* __restrict__ proj_w, float* __restrict__ out, int N) {
    int idx = blockIdx.x * blockDim.x + threadIdx.x;
    if (idx >= N * 4) return;
    int n = idx >> 2, d = idx & 3;
    float den[4];
#pragma unroll
    for (int h = 0; h < 4; h++) den[h] = denG[n * 4 + h];
    float oc[8];
#pragma unroll
    for (int m2 = 0; m2 < 8; m2++) {
        int h = m2 >> 1;
        float dd = den[h];
        float nm = numG[(size_t)n * 32 + h * 8 + (m2 & 1) * 4 + d];
        oc[m2] = dd > 0.0f ? nm / dd : 0.0f;   // empty segment -> 0 (matches ref)
    }
    int ro = (d == 0) ? 0 : 8;                 // ix2 = [0,1,1,1]
#pragma unroll
    for (int m = 0; m < 8; m++) {
        float r = 0.0f;
#pragma unroll
        for (int m2 = 0; m2 < 8; m2++) r += proj_w[(ro + m) * 8 + m2] * oc[m2];
        out[(size_t)n * 32 + m * 4 + d] = r;
    }
}

// ---------------- launcher ----------------
extern "C" void kernel_launch(void* const* d_in, const int* in_sizes, int n_in,
                              void* d_out, int out_size) {
    const int*   src        = (const int*)d_in[0];
    const int*   dst        = (const int*)d_in[1];
    const float* basis      = (const float*)d_in[2];
    const float* features   = (const float*)d_in[3];
    const float* edge_feats = (const float*)d_in[4];
    const float* w1         = (const float*)d_in[5];
    const float* b1         = (const float*)d_in[6];
    const float* w2         = (const float*)d_in[7];
    const float* b2         = (const float*)d_in[8];
    // d_in[9] = ln_w, d_in[10] = ln_b
    const float* ln_w       = (const float*)d_in[9];
    const float* ln_b       = (const float*)d_in[10];
    const float* proj_w     = (const float*)d_in[11];
    float* out = (float*)d_out;

    int E = in_sizes[0];
    int N = in_sizes[3] / 32;

    init_kernel<<<(N * 32 + 255) / 256, 256>>>(N);
    node_ln_kernel<<<(N + 127) / 128, 128>>>(features, ln_w, ln_b, N);

    size_t smbytes = SM_TOTAL * sizeof(float);
    cudaFuncSetAttribute(edge_kernel, cudaFuncAttributeMaxDynamicSharedMemorySize, (int)smbytes);
    edge_kernel<<<(E + 31) / 32, 256, smbytes>>>(src, dst, basis, edge_feats,
                                                 w1, b1, w2, b2, E);

    attn_kernel<<<(E * 4 + 255) / 256, 256>>>(dst, E);
    out_kernel<<<(N * 4 + 255) / 256, 256>>>(proj_w, out, N);
}

// round 2
// speedup vs baseline: 3.0674x; 3.0674x over previous
#include <cuda_runtime.h>
#include <cuda_bf16.h>
#include <math_constants.h>

#define NN 40000
#define NE 320000

// ---------------- scratch (device globals; no allocation allowed) ----------------
__device__ float fG[NN * 32];
__device__ float scoresG[NE * 4];
__device__ float vG[NE * 32];
__device__ float smaxG[NN * 4];
__device__ float denG[NN * 4];
__device__ float numG[NN * 32];
// w2 split to bf16 hi/lo, permuted to m16n8k16 B-fragment layout:
// uint2 index = ((i_nt*4 + kstep)*32 + lane), .x = b0 pair, .y = b1 pair
__device__ uint2 w2pHiG[96 * 4 * 32];
__device__ uint2 w2pLoG[96 * 4 * 32];

__device__ __forceinline__ void atomicMaxF(float* a, float v) {
    if (v == 0.0f) v = 0.0f;
    if (v >= 0.0f) atomicMax((int*)a, __float_as_int(v));
    else           atomicMin((unsigned int*)a, __float_as_uint(v));
}

__device__ __forceinline__ void mma_bf16(float* c, const unsigned* a, unsigned b0, unsigned b1) {
    asm volatile("mma.sync.aligned.m16n8k16.row.col.f32.bf16.bf16.f32 "
                 "{%0,%1,%2,%3}, {%4,%5,%6,%7}, {%8,%9}, {%0,%1,%2,%3};\n"
                 : "+f"(c[0]), "+f"(c[1]), "+f"(c[2]), "+f"(c[3])
                 : "r"(a[0]), "r"(a[1]), "r"(a[2]), "r"(a[3]), "r"(b0), "r"(b1));
}

// ---------------- init scratch ----------------
__global__ void init_kernel(int N) {
    int i = blockIdx.x * blockDim.x + threadIdx.x;
    if (i < N * 4) { smaxG[i] = -CUDART_INF_F; denG[i] = 0.0f; }
    if (i < N * 32) numG[i] = 0.0f;
}

// ---------------- prep: split w2 into bf16 hi/lo fragment layout ----------------
__global__ void prep_w2_kernel(const float* __restrict__ w2) {
    int idx = blockIdx.x * 256 + threadIdx.x;
    if (idx >= 768 * 32) return;
    int c = idx >> 5, kp = idx & 31;             // c: w2 row (0..767), kp: k-pair (0..31)
    float v0 = w2[c * 64 + 2 * kp];
    float v1 = w2[c * 64 + 2 * kp + 1];
    __nv_bfloat16 h0 = __float2bfloat16_rn(v0);
    __nv_bfloat16 h1 = __float2bfloat16_rn(v1);
    __nv_bfloat16 l0 = __float2bfloat16_rn(v0 - __bfloat162float(h0));
    __nv_bfloat16 l1 = __float2bfloat16_rn(v1 - __bfloat162float(h1));
    unsigned hiu = ((unsigned)__bfloat16_as_ushort(h1) << 16) | (unsigned)__bfloat16_as_ushort(h0);
    unsigned lou = ((unsigned)__bfloat16_as_ushort(l1) << 16) | (unsigned)__bfloat16_as_ushort(l0);
    int i_nt = c >> 3, g = c & 7;                // 8-col group, col within group
    int ks = kp >> 3;                            // k-step (16 k per step)
    int tq = kp & 3;                             // threadID_in_group
    int half = (kp >> 2) & 1;                    // b0 (k<8) vs b1 (k>=8)
    int frag = (i_nt * 4 + ks) * 32 + g * 4 + tq;
    ((unsigned*)w2pHiG)[frag * 2 + half] = hiu;
    ((unsigned*)w2pLoG)[frag * 2 + half] = lou;
}

// ---------------- node-wise equivariant layer norm ----------------
__global__ void node_ln_kernel(const float* __restrict__ features,
                               const float* __restrict__ ln_w,
                               const float* __restrict__ ln_b, int N) {
    int n = blockIdx.x * blockDim.x + threadIdx.x;
    if (n >= N) return;
    float f[32];
    const float4* fp = (const float4*)(features + (size_t)n * 32);
#pragma unroll
    for (int q = 0; q < 8; q++) {
        float4 v = fp[q];
        f[q * 4 + 0] = v.x; f[q * 4 + 1] = v.y; f[q * 4 + 2] = v.z; f[q * 4 + 3] = v.w;
    }
    float nf[16];
#pragma unroll
    for (int m = 0; m < 8; m++) {
        nf[2 * m]     = sqrtf(f[m * 4] * f[m * 4]);
        nf[2 * m + 1] = sqrtf(f[m * 4 + 1] * f[m * 4 + 1] +
                              f[m * 4 + 2] * f[m * 4 + 2] +
                              f[m * 4 + 3] * f[m * 4 + 3]);
    }
    float ratio[16];
#pragma unroll
    for (int g = 0; g < 2; g++) {
        float mu = 0.0f;
#pragma unroll
        for (int b = 0; b < 8; b++) mu += nf[8 * g + b];
        mu *= 0.125f;
        float var = 0.0f;
#pragma unroll
        for (int b = 0; b < 8; b++) { float d = nf[8 * g + b] - mu; var += d * d; }
        var *= 0.125f;
        float rs = rsqrtf(var + 1e-5f);
#pragma unroll
        for (int b = 0; b < 8; b++) {
            float l = (nf[8 * g + b] - mu) * rs * ln_w[b] + ln_b[b];
            l = fmaxf(l, 0.0f);
            ratio[8 * g + b] = l / (nf[8 * g + b] + 1e-8f);
        }
    }
    float4* op = (float4*)(fG + (size_t)n * 32);
#pragma unroll
    for (int m = 0; m < 8; m++) {
        float4 v;
        v.x = f[m * 4 + 0] * ratio[2 * m];
        v.y = f[m * 4 + 1] * ratio[2 * m + 1];
        v.z = f[m * 4 + 2] * ratio[2 * m + 1];
        v.w = f[m * 4 + 3] * ratio[2 * m + 1];
        op[m] = v;
    }
}

// ---------------- fused per-edge kernel: 64 edges / 256 threads ----------------
// smem layout (float indices)
#define SW1   0       // w1 transposed [k][j], 32*64
#define SB1   2048    // 64
#define SB2   2112    // 768
#define STMP  2880    // tmp [e][132] (32 j * 4 d, padded), 64*132=8448
#define SH2H  11328   // h hi bf16x2 [e][34] uints
#define SH2L  13504   // h lo
#define SSTG  15680   // stage union: (ef|fU|basis) then conv
#define SEF   (SSTG)          // 64*32
#define SFU   (SSTG + 2048)   // 64*32
#define SBAS  (SSTG + 4096)   // 64*64
#define SCONV (SSTG)          // 64*100 = 6400 <= 8192
#define STOT  23872

__global__ __launch_bounds__(256, 2)
void edge_kernel(const int* __restrict__ src, const int* __restrict__ dst,
                 const float* __restrict__ basis, const float* __restrict__ edge_feats,
                 const float* __restrict__ w1, const float* __restrict__ b1,
                 const float* __restrict__ b2, int E) {
    extern __shared__ float sm[];
    unsigned* smu = (unsigned*)sm;
    int t = threadIdx.x;
    int e0 = blockIdx.x * 64;

    // stage w1 (transposed), b1, b2
    for (int idx = t; idx < 2048; idx += 256) {
        int j = idx >> 5, k = idx & 31;
        sm[SW1 + k * 64 + j] = w1[idx];
    }
    if (t < 64) sm[SB1 + t] = b1[t];
    for (int idx = t; idx < 768; idx += 256) sm[SB2 + idx] = b2[idx];

    int el = t >> 2, part = t & 3;   // 64 edges x 4 parts
    int e = e0 + el;
    int ec = e < E ? e : E - 1;

    // stage ef, gathered features, basis
    {
        const float4* efp = (const float4*)edge_feats + (size_t)ec * 8;
        *(float4*)&sm[SEF + el * 32 + part * 8]     = __ldg(efp + part * 2);
        *(float4*)&sm[SEF + el * 32 + part * 8 + 4] = __ldg(efp + part * 2 + 1);
        int s = __ldg(src + ec);
        const float4* fp = (const float4*)fG + (size_t)s * 8;
        *(float4*)&sm[SFU + el * 32 + part * 8]     = fp[part * 2];
        *(float4*)&sm[SFU + el * 32 + part * 8 + 4] = fp[part * 2 + 1];
        const float4* bp = (const float4*)basis + (size_t)ec * 16;
#pragma unroll
        for (int q = 0; q < 4; q++)
            *(float4*)&sm[SBAS + el * 64 + part * 16 + q * 4] = __ldg(bp + part * 4 + q);
    }
    __syncthreads();

    // h = relu(ef @ w1^T + b1); split into bf16 hi/lo pairs. 16 j per thread.
    {
        float ef[32];
#pragma unroll
        for (int k = 0; k < 32; k++) ef[k] = sm[SEF + el * 32 + k];
        int j0 = part * 16;
        float acc[16];
#pragma unroll
        for (int jj = 0; jj < 16; jj++) acc[jj] = sm[SB1 + j0 + jj];
#pragma unroll
        for (int k = 0; k < 32; k++) {
            float ev = ef[k];
#pragma unroll
            for (int q = 0; q < 4; q++) {
                float4 wv = *(const float4*)&sm[SW1 + k * 64 + j0 + q * 4];
                acc[q * 4 + 0] += ev * wv.x; acc[q * 4 + 1] += ev * wv.y;
                acc[q * 4 + 2] += ev * wv.z; acc[q * 4 + 3] += ev * wv.w;
            }
        }
#pragma unroll
        for (int q = 0; q < 8; q++) {
            float v0 = fmaxf(acc[2 * q], 0.f), v1 = fmaxf(acc[2 * q + 1], 0.f);
            __nv_bfloat16 h0 = __float2bfloat16_rn(v0);
            __nv_bfloat16 h1 = __float2bfloat16_rn(v1);
            __nv_bfloat16 l0 = __float2bfloat16_rn(v0 - __bfloat162float(h0));
            __nv_bfloat16 l1 = __float2bfloat16_rn(v1 - __bfloat162float(h1));
            smu[SH2H + el * 34 + part * 8 + q] =
                ((unsigned)__bfloat16_as_ushort(h1) << 16) | (unsigned)__bfloat16_as_ushort(h0);
            smu[SH2L + el * 34 + part * 8 + q] =
                ((unsigned)__bfloat16_as_ushort(l1) << 16) | (unsigned)__bfloat16_as_ushort(l0);
        }
    }
    // tmp[e][j][d] = sum_dd fU[e][m*4+dd] * basis[e][dd*16 + p*4 + d], j = m*4+p
#pragma unroll
    for (int jj = 0; jj < 8; jj++) {
        int j = part * 8 + jj;
        int m = j >> 2, pp = j & 3;
        float o0 = 0.f, o1 = 0.f, o2 = 0.f, o3 = 0.f;
#pragma unroll
        for (int dd = 0; dd < 4; dd++) {
            float fv = sm[SFU + el * 32 + m * 4 + dd];
            o0 += fv * sm[SBAS + el * 64 + dd * 16 + pp * 4 + 0];
            o1 += fv * sm[SBAS + el * 64 + dd * 16 + pp * 4 + 1];
            o2 += fv * sm[SBAS + el * 64 + dd * 16 + pp * 4 + 2];
            o3 += fv * sm[SBAS + el * 64 + dd * 16 + pp * 4 + 3];
        }
        sm[STMP + el * 132 + j * 4 + 0] = o0;
        sm[STMP + el * 132 + j * 4 + 1] = o1;
        sm[STMP + el * 132 + j * 4 + 2] = o2;
        sm[STMP + el * 132 + j * 4 + 3] = o3;
    }
    __syncthreads();

    // ---- Phase B: rw GEMM on tensor cores (split-bf16, 3 products) + fused contraction ----
    {
        int w = t >> 5, lane = t & 31, g = lane >> 2, tq = lane & 3;
#pragma unroll 1
        for (int p = 0; p < 2; p++) {
            unsigned Ah[2][4][4], Al[2][4][4];
#pragma unroll
            for (int mm = 0; mm < 2; mm++) {
                int r0 = p * 32 + mm * 16 + g;
#pragma unroll
                for (int ks = 0; ks < 4; ks++) {
                    Ah[mm][ks][0] = smu[SH2H + r0 * 34 + ks * 8 + tq];
                    Ah[mm][ks][1] = smu[SH2H + (r0 + 8) * 34 + ks * 8 + tq];
                    Ah[mm][ks][2] = smu[SH2H + r0 * 34 + ks * 8 + 4 + tq];
                    Ah[mm][ks][3] = smu[SH2H + (r0 + 8) * 34 + ks * 8 + 4 + tq];
                    Al[mm][ks][0] = smu[SH2L + r0 * 34 + ks * 8 + tq];
                    Al[mm][ks][1] = smu[SH2L + (r0 + 8) * 34 + ks * 8 + tq];
                    Al[mm][ks][2] = smu[SH2L + r0 * 34 + ks * 8 + 4 + tq];
                    Al[mm][ks][3] = smu[SH2L + (r0 + 8) * 34 + ks * 8 + 4 + tq];
                }
            }
#pragma unroll 1
            for (int il = 0; il < 3; il++) {
                int i = w * 3 + il;
                float cp[4][4];
#pragma unroll
                for (int x = 0; x < 4; x++)
#pragma unroll
                    for (int d = 0; d < 4; d++) cp[x][d] = 0.f;
#pragma unroll
                for (int nt = 0; nt < 4; nt++) {
                    int cb = i * 32 + nt * 8;
                    float bz0 = sm[SB2 + cb + 2 * tq];
                    float bz1 = sm[SB2 + cb + 2 * tq + 1];
                    float acc[2][4];
#pragma unroll
                    for (int mm = 0; mm < 2; mm++) {
                        acc[mm][0] = bz0; acc[mm][1] = bz1;
                        acc[mm][2] = bz0; acc[mm][3] = bz1;
                    }
                    int fb = (i * 16 + nt * 4) * 32 + lane;
#pragma unroll
                    for (int ks = 0; ks < 4; ks++) {
                        uint2 bh = __ldg(w2pHiG + fb + ks * 32);
                        uint2 bl = __ldg(w2pLoG + fb + ks * 32);
#pragma unroll
                        for (int mm = 0; mm < 2; mm++) {
                            mma_bf16(acc[mm], Ah[mm][ks], bh.x, bh.y);
                            mma_bf16(acc[mm], Ah[mm][ks], bl.x, bl.y);
                            mma_bf16(acc[mm], Al[mm][ks], bh.x, bh.y);
                        }
                    }
                    int jl = nt * 8 + 2 * tq;
#pragma unroll
                    for (int mm = 0; mm < 2; mm++) {
                        int er = p * 32 + mm * 16 + g;
                        float4 t00 = *(const float4*)&sm[STMP + er * 132 + jl * 4];
                        float4 t01 = *(const float4*)&sm[STMP + er * 132 + jl * 4 + 4];
                        float4 t10 = *(const float4*)&sm[STMP + (er + 8) * 132 + jl * 4];
                        float4 t11 = *(const float4*)&sm[STMP + (er + 8) * 132 + jl * 4 + 4];
                        cp[mm * 2][0] += acc[mm][0] * t00.x + acc[mm][1] * t01.x;
                        cp[mm * 2][1] += acc[mm][0] * t00.y + acc[mm][1] * t01.y;
                        cp[mm * 2][2] += acc[mm][0] * t00.z + acc[mm][1] * t01.z;
                        cp[mm * 2][3] += acc[mm][0] * t00.w + acc[mm][1] * t01.w;
                        cp[mm * 2 + 1][0] += acc[mm][2] * t10.x + acc[mm][3] * t11.x;
                        cp[mm * 2 + 1][1] += acc[mm][2] * t10.y + acc[mm][3] * t11.y;
                        cp[mm * 2 + 1][2] += acc[mm][2] * t10.z + acc[mm][3] * t11.z;
                        cp[mm * 2 + 1][3] += acc[mm][2] * t10.w + acc[mm][3] * t11.w;
                    }
                }
                // reduce over the 4 quad lanes (j-columns), then lane tq==0 writes
#pragma unroll
                for (int x = 0; x < 4; x++)
#pragma unroll
                    for (int d = 0; d < 4; d++) {
                        float v = cp[x][d];
                        v += __shfl_xor_sync(0xffffffffu, v, 1);
                        v += __shfl_xor_sync(0xffffffffu, v, 2);
                        cp[x][d] = v;
                    }
                if (tq == 0) {
#pragma unroll
                    for (int mm = 0; mm < 2; mm++)
#pragma unroll
                        for (int rr = 0; rr < 2; rr++) {
                            int er = p * 32 + mm * 16 + g + rr * 8;
                            *(float4*)&sm[SCONV + er * 100 + i * 4] =
                                make_float4(cp[mm * 2 + rr][0], cp[mm * 2 + rr][1],
                                            cp[mm * 2 + rr][2], cp[mm * 2 + rr][3]);
                        }
                }
            }
        }
    }
    __syncthreads();

    // ---- Phase C: scores + v ----
    {
        int el2 = t >> 2, hh = t & 3;
        float sc = 0.0f;
#pragma unroll
        for (int x = 0; x < 8; x++) {
            int m = 2 * hh + (x >> 2), d = x & 3;
            sc += sm[SCONV + el2 * 100 + m * 4 + d] *
                  sm[SCONV + el2 * 100 + (8 + m) * 4 + d];
        }
        sc *= 0.17677669529663687f;          // 32^-0.5
        sc = sc >= 0.0f ? sc : 0.2f * sc;    // LeakyReLU(0.2)
        int ee = e0 + el2;
        if (ee < E) {
            scoresG[ee * 4 + hh] = sc;
            atomicMaxF(&smaxG[dst[ee] * 4 + hh], sc);
        }
    }
    if (e < E) {
        *(float4*)&vG[(size_t)e * 32 + part * 8] =
            *(const float4*)&sm[SCONV + el * 100 + 64 + part * 8];
        *(float4*)&vG[(size_t)e * 32 + part * 8 + 4] =
            *(const float4*)&sm[SCONV + el * 100 + 64 + part * 8 + 4];
    }
}

// ---------------- softmax accumulate ----------------
__global__ void attn_kernel(const int* __restrict__ dst, int E) {
    int idx = blockIdx.x * blockDim.x + threadIdx.x;
    if (idx >= E * 4) return;
    int e = idx >> 2, h = idx & 3;
    int dn = dst[e];
    float ex = expf(scoresG[idx] - smaxG[dn * 4 + h]);
    atomicAdd(&denG[dn * 4 + h], ex);
    const float4* vp = (const float4*)(vG + (size_t)e * 32 + h * 8);
    float4 va = vp[0], vb = vp[1];
    float* np = numG + (size_t)dn * 32 + h * 8;
    atomicAdd(np + 0, ex * va.x);
    atomicAdd(np + 1, ex * va.y);
    atomicAdd(np + 2, ex * va.z);
    atomicAdd(np + 3, ex * va.w);
    atomicAdd(np + 4, ex * vb.x);
    atomicAdd(np + 5, ex * vb.y);
    atomicAdd(np + 6, ex * vb.z);
    atomicAdd(np + 7, ex * vb.w);
}

// ---------------- node output ----------------
__global__ void out_kernel(const float* __restrict__ proj_w, float* __restrict__ out, int N) {
    int idx = blockIdx.x * blockDim.x + threadIdx.x;
    if (idx >= N * 4) return;
    int n = idx >> 2, d = idx & 3;
    float den[4];
#pragma unroll
    for (int h = 0; h < 4; h++) den[h] = denG[n * 4 + h];
    float oc[8];
#pragma unroll
    for (int m2 = 0; m2 < 8; m2++) {
        int h = m2 >> 1;
        float dd = den[h];
        float nm = numG[(size_t)n * 32 + h * 8 + (m2 & 1) * 4 + d];
        oc[m2] = dd > 0.0f ? nm / dd : 0.0f;
    }
    int ro = (d == 0) ? 0 : 8;                 // ix2 = [0,1,1,1]
#pragma unroll
    for (int m = 0; m < 8; m++) {
        float r = 0.0f;
#pragma unroll
        for (int m2 = 0; m2 < 8; m2++) r += proj_w[(ro + m) * 8 + m2] * oc[m2];
        out[(size_t)n * 32 + m * 4 + d] = r;
    }
}

// ---------------- launcher ----------------
extern "C" void kernel_launch(void* const* d_in, const int* in_sizes, int n_in,
                              void* d_out, int out_size) {
    const int*   src        = (const int*)d_in[0];
    const int*   dst        = (const int*)d_in[1];
    const float* basis      = (const float*)d_in[2];
    const float* features   = (const float*)d_in[3];
    const float* edge_feats = (const float*)d_in[4];
    const float* w1         = (const float*)d_in[5];
    const float* b1         = (const float*)d_in[6];
    const float* w2         = (const float*)d_in[7];
    const float* b2         = (const float*)d_in[8];
    const float* ln_w       = (const float*)d_in[9];
    const float* ln_b       = (const float*)d_in[10];
    const float* proj_w     = (const float*)d_in[11];
    float* out = (float*)d_out;

    int E = in_sizes[0];
    int N = in_sizes[3] / 32;

    init_kernel<<<(N * 32 + 255) / 256, 256>>>(N);
    prep_w2_kernel<<<96, 256>>>(w2);
    node_ln_kernel<<<(N + 127) / 128, 128>>>(features, ln_w, ln_b, N);

    size_t smbytes = STOT * sizeof(float);
    cudaFuncSetAttribute(edge_kernel, cudaFuncAttributeMaxDynamicSharedMemorySize, (int)smbytes);
    edge_kernel<<<(E + 63) / 64, 256, smbytes>>>(src, dst, basis, edge_feats,
                                                 w1, b1, b2, E);

    attn_kernel<<<(E * 4 + 255) / 256, 256>>>(dst, E);
    out_kernel<<<(N * 4 + 255) / 256, 256>>>(proj_w, out, N);
}

// round 3
// speedup vs baseline: 4.0405x; 1.3172x over previous
#include <cuda_runtime.h>
#include <cuda_bf16.h>
#include <math_constants.h>

#define NN 40000
#define NE 320000

// ---------------- scratch (device globals; no allocation allowed) ----------------
__device__ float fG[NN * 32];
__device__ float scoresG[NE * 4];
__device__ float vG[NE * 32];
__device__ float smaxG[NN * 4];
__device__ float accG[NN * 48];   // per (n,h): [0..7]=num, [8]=den, [9..11] pad
// w2 packed: uint4 = (bhi0, bhi1, blo0, blo1), fragment-ordered, j-major ntiles:
// ntile t = j*3 + ig  (i = ig*8 + g), index = ((t*4 + ks)*32 + g*4 + tq)
__device__ uint4 w2pG[96 * 4 * 32];

__device__ __forceinline__ void atomicMaxF(float* a, float v) {
    if (v == 0.0f) v = 0.0f;
    if (v >= 0.0f) atomicMax((int*)a, __float_as_int(v));
    else           atomicMin((unsigned int*)a, __float_as_uint(v));
}

__device__ __forceinline__ void redAdd4(float* p, float a, float b, float c, float d) {
    asm volatile("red.global.add.v4.f32 [%0], {%1,%2,%3,%4};"
                 :: "l"(p), "f"(a), "f"(b), "f"(c), "f"(d) : "memory");
}

__device__ __forceinline__ void mma_bf16(float* c, const unsigned* a, unsigned b0, unsigned b1) {
    asm volatile("mma.sync.aligned.m16n8k16.row.col.f32.bf16.bf16.f32 "
                 "{%0,%1,%2,%3}, {%4,%5,%6,%7}, {%8,%9}, {%0,%1,%2,%3};\n"
                 : "+f"(c[0]), "+f"(c[1]), "+f"(c[2]), "+f"(c[3])
                 : "r"(a[0]), "r"(a[1]), "r"(a[2]), "r"(a[3]), "r"(b0), "r"(b1));
}

// ---------------- init scratch ----------------
__global__ void init_kernel(int N) {
    int i = blockIdx.x * blockDim.x + threadIdx.x;
    if (i < N * 4) smaxG[i] = -CUDART_INF_F;
    if (i < N * 48) accG[i] = 0.0f;
}

// ---------------- prep: split w2 to bf16 hi/lo, j-major fragment layout ----------------
__global__ void prep_w2_kernel(const float* __restrict__ w2) {
    int idx = blockIdx.x * 256 + threadIdx.x;
    if (idx >= 768 * 32) return;
    int o = idx >> 5, kp = idx & 31;             // o: w2 row, kp: k-pair
    float v0 = w2[o * 64 + 2 * kp];
    float v1 = w2[o * 64 + 2 * kp + 1];
    __nv_bfloat16 h0 = __float2bfloat16_rn(v0);
    __nv_bfloat16 h1 = __float2bfloat16_rn(v1);
    __nv_bfloat16 l0 = __float2bfloat16_rn(v0 - __bfloat162float(h0));
    __nv_bfloat16 l1 = __float2bfloat16_rn(v1 - __bfloat162float(h1));
    unsigned hiu = ((unsigned)__bfloat16_as_ushort(h1) << 16) | (unsigned)__bfloat16_as_ushort(h0);
    unsigned lou = ((unsigned)__bfloat16_as_ushort(l1) << 16) | (unsigned)__bfloat16_as_ushort(l0);
    int i = o >> 5, j = o & 31;                  // o = i*32 + j
    int t = j * 3 + (i >> 3);                    // j-major ntile
    int g = i & 7;                               // column within ntile
    int ks = kp >> 3;                            // 16-k step
    int tq = kp & 3;
    int half = (kp >> 2) & 1;                    // b0 (k<8) vs b1 (k>=8)
    int frag = (t * 4 + ks) * 32 + g * 4 + tq;
    ((unsigned*)w2pG)[frag * 4 + half]     = hiu;
    ((unsigned*)w2pG)[frag * 4 + 2 + half] = lou;
}

// ---------------- node-wise equivariant layer norm ----------------
__global__ void node_ln_kernel(const float* __restrict__ features,
                               const float* __restrict__ ln_w,
                               const float* __restrict__ ln_b, int N) {
    int n = blockIdx.x * blockDim.x + threadIdx.x;
    if (n >= N) return;
    float f[32];
    const float4* fp = (const float4*)(features + (size_t)n * 32);
#pragma unroll
    for (int q = 0; q < 8; q++) {
        float4 v = fp[q];
        f[q * 4 + 0] = v.x; f[q * 4 + 1] = v.y; f[q * 4 + 2] = v.z; f[q * 4 + 3] = v.w;
    }
    float nf[16];
#pragma unroll
    for (int m = 0; m < 8; m++) {
        nf[2 * m]     = sqrtf(f[m * 4] * f[m * 4]);
        nf[2 * m + 1] = sqrtf(f[m * 4 + 1] * f[m * 4 + 1] +
                              f[m * 4 + 2] * f[m * 4 + 2] +
                              f[m * 4 + 3] * f[m * 4 + 3]);
    }
    float ratio[16];
#pragma unroll
    for (int g = 0; g < 2; g++) {
        float mu = 0.0f;
#pragma unroll
        for (int b = 0; b < 8; b++) mu += nf[8 * g + b];
        mu *= 0.125f;
        float var = 0.0f;
#pragma unroll
        for (int b = 0; b < 8; b++) { float d = nf[8 * g + b] - mu; var += d * d; }
        var *= 0.125f;
        float rs = rsqrtf(var + 1e-5f);
#pragma unroll
        for (int b = 0; b < 8; b++) {
            float l = (nf[8 * g + b] - mu) * rs * ln_w[b] + ln_b[b];
            l = fmaxf(l, 0.0f);
            ratio[8 * g + b] = l / (nf[8 * g + b] + 1e-8f);
        }
    }
    float4* op = (float4*)(fG + (size_t)n * 32);
#pragma unroll
    for (int m = 0; m < 8; m++) {
        float4 v;
        v.x = f[m * 4 + 0] * ratio[2 * m];
        v.y = f[m * 4 + 1] * ratio[2 * m + 1];
        v.z = f[m * 4 + 2] * ratio[2 * m + 1];
        v.w = f[m * 4 + 3] * ratio[2 * m + 1];
        op[m] = v;
    }
}

// ---------------- fused per-edge kernel: 64 edges / 192 threads (6 warps) ----------------
// smem layout (float/uint indices)
#define SW1   0       // w1 transposed [k][j], 32*64
#define SB1   2048    // 64
#define SB2   2112    // 768
#define STMP  2880    // tmp [e][132] (32 j * 4 d, padded) -> 2880+8448=11328
#define SH2H  11328   // h hi bf16x2 [e][36] uints -> 13632
#define SH2L  13632   // h lo -> 15936
#define SSRC  15936   // 64 src ints -> 16000
#define SSTG  16000   // staging union, 8192 floats
#define SEF   (SSTG)          // 64*32
#define SFU   (SSTG + 2048)   // 64*32
#define SBAS  (SSTG + 4096)   // 64*64
#define SCONV (SSTG)          // 64*100 = 6400 (reuses staging)
#define STOT  24192           // 96768 bytes

__global__ __launch_bounds__(192, 2)
void edge_kernel(const int* __restrict__ src, const int* __restrict__ dst,
                 const float* __restrict__ basis, const float* __restrict__ edge_feats,
                 const float* __restrict__ w1, const float* __restrict__ b1,
                 const float* __restrict__ b2, int E) {
    extern __shared__ float sm[];
    unsigned* smu = (unsigned*)sm;
    int t = threadIdx.x;
    int e0 = blockIdx.x * 64;

    // ---- stage weights + per-edge inputs ----
    for (int idx = t; idx < 2048; idx += 192) {
        int j = idx >> 5, k = idx & 31;
        sm[SW1 + k * 64 + j] = w1[idx];
    }
    if (t < 64) {
        sm[SB1 + t] = b1[t];
        int ee = e0 + t;
        ((int*)&sm[SSRC])[t] = __ldg(src + (ee < E ? ee : E - 1));
    }
    for (int idx = t; idx < 768; idx += 192) sm[SB2 + idx] = b2[idx];
    __syncthreads();

    for (int idx = t; idx < 512; idx += 192) {
        int el = idx >> 3, q = idx & 7;
        int ee = e0 + el; int ec = ee < E ? ee : E - 1;
        *(float4*)&sm[SEF + el * 32 + q * 4] =
            __ldg((const float4*)edge_feats + (size_t)ec * 8 + q);
        int s = ((const int*)&sm[SSRC])[el];
        *(float4*)&sm[SFU + el * 32 + q * 4] = ((const float4*)fG)[(size_t)s * 8 + q];
    }
    for (int idx = t; idx < 1024; idx += 192) {
        int el = idx >> 4, q = idx & 15;
        int ee = e0 + el; int ec = ee < E ? ee : E - 1;
        *(float4*)&sm[SBAS + el * 64 + q * 4] =
            __ldg((const float4*)basis + (size_t)ec * 16 + q);
    }
    __syncthreads();

    // ---- phase A: h = relu(ef@w1^T+b1) -> bf16 hi/lo;  tmp = fU x basis ----
    if (t < 128) {
        int el = t >> 1, part = t & 1, j0 = part * 32;
        float ef[32];
#pragma unroll
        for (int k = 0; k < 32; k++) ef[k] = sm[SEF + el * 32 + k];
        float acc[32];
#pragma unroll
        for (int jj = 0; jj < 32; jj++) acc[jj] = sm[SB1 + j0 + jj];
#pragma unroll
        for (int k = 0; k < 32; k++) {
            float ev = ef[k];
#pragma unroll
            for (int q = 0; q < 8; q++) {
                float4 wv = *(const float4*)&sm[SW1 + k * 64 + j0 + q * 4];
                acc[q * 4 + 0] += ev * wv.x; acc[q * 4 + 1] += ev * wv.y;
                acc[q * 4 + 2] += ev * wv.z; acc[q * 4 + 3] += ev * wv.w;
            }
        }
#pragma unroll
        for (int q = 0; q < 16; q++) {
            float v0 = fmaxf(acc[2 * q], 0.f), v1 = fmaxf(acc[2 * q + 1], 0.f);
            __nv_bfloat16 h0 = __float2bfloat16_rn(v0);
            __nv_bfloat16 h1 = __float2bfloat16_rn(v1);
            __nv_bfloat16 l0 = __float2bfloat16_rn(v0 - __bfloat162float(h0));
            __nv_bfloat16 l1 = __float2bfloat16_rn(v1 - __bfloat162float(h1));
            smu[SH2H + el * 36 + part * 16 + q] =
                ((unsigned)__bfloat16_as_ushort(h1) << 16) | (unsigned)__bfloat16_as_ushort(h0);
            smu[SH2L + el * 36 + part * 16 + q] =
                ((unsigned)__bfloat16_as_ushort(l1) << 16) | (unsigned)__bfloat16_as_ushort(l0);
        }
    } else {
        for (int idx = t - 128; idx < 2048; idx += 64) {
            int el = idx >> 5, j = idx & 31;
            int m = j >> 2, pp = j & 3;
            float o0 = 0.f, o1 = 0.f, o2 = 0.f, o3 = 0.f;
#pragma unroll
            for (int dd = 0; dd < 4; dd++) {
                float fv = sm[SFU + el * 32 + m * 4 + dd];
                o0 += fv * sm[SBAS + el * 64 + dd * 16 + pp * 4 + 0];
                o1 += fv * sm[SBAS + el * 64 + dd * 16 + pp * 4 + 1];
                o2 += fv * sm[SBAS + el * 64 + dd * 16 + pp * 4 + 2];
                o3 += fv * sm[SBAS + el * 64 + dd * 16 + pp * 4 + 3];
            }
            *(float4*)&sm[STMP + el * 132 + j * 4] = make_float4(o0, o1, o2, o3);
        }
    }
    __syncthreads();

    // ---- phase B: rw GEMM (tensor cores, split bf16) + fused j-local contraction ----
    {
        int w = t >> 5, lane = t & 31, g = lane >> 2, tq = lane & 3;
        int ig = w % 3, ehalf = w / 3;        // warp = (i-group, edge-half)
        int i0 = ig * 8 + 2 * tq;

        // A fragments for 2 m-tiles (32 edges), all 4 k-steps, hi+lo
        unsigned Ah[2][4][4], Al[2][4][4];
#pragma unroll
        for (int mt = 0; mt < 2; mt++) {
            int r0 = (ehalf * 2 + mt) * 16 + g;
#pragma unroll
            for (int ks = 0; ks < 4; ks++) {
                Ah[mt][ks][0] = smu[SH2H + r0 * 36 + ks * 8 + tq];
                Ah[mt][ks][1] = smu[SH2H + (r0 + 8) * 36 + ks * 8 + tq];
                Ah[mt][ks][2] = smu[SH2H + r0 * 36 + ks * 8 + 4 + tq];
                Ah[mt][ks][3] = smu[SH2H + (r0 + 8) * 36 + ks * 8 + 4 + tq];
                Al[mt][ks][0] = smu[SH2L + r0 * 36 + ks * 8 + tq];
                Al[mt][ks][1] = smu[SH2L + (r0 + 8) * 36 + ks * 8 + tq];
                Al[mt][ks][2] = smu[SH2L + r0 * 36 + ks * 8 + 4 + tq];
                Al[mt][ks][3] = smu[SH2L + (r0 + 8) * 36 + ks * 8 + 4 + tq];
            }
        }

        float cp[2][16];                       // [mt][(e01)*8 + (i01)*4 + d]
#pragma unroll
        for (int mt = 0; mt < 2; mt++)
#pragma unroll
            for (int x = 0; x < 16; x++) cp[mt][x] = 0.f;

#pragma unroll 1
        for (int j = 0; j < 32; j++) {
            float bz0 = sm[SB2 + i0 * 32 + j];
            float bz1 = sm[SB2 + (i0 + 1) * 32 + j];
            float ahh[2][4], ahl[2][4], alh[2][4];
#pragma unroll
            for (int mt = 0; mt < 2; mt++) {
                ahh[mt][0] = bz0; ahh[mt][1] = bz1; ahh[mt][2] = bz0; ahh[mt][3] = bz1;
                ahl[mt][0] = ahl[mt][1] = ahl[mt][2] = ahl[mt][3] = 0.f;
                alh[mt][0] = alh[mt][1] = alh[mt][2] = alh[mt][3] = 0.f;
            }
            const uint4* wp = w2pG + ((j * 3 + ig) * 4) * 32 + lane;
#pragma unroll
            for (int ks = 0; ks < 4; ks++) {
                uint4 bv = __ldg(wp + ks * 32);
#pragma unroll
                for (int mt = 0; mt < 2; mt++) {
                    mma_bf16(ahh[mt], Ah[mt][ks], bv.x, bv.y);
                    mma_bf16(ahl[mt], Ah[mt][ks], bv.z, bv.w);
                    mma_bf16(alh[mt], Al[mt][ks], bv.x, bv.y);
                }
            }
#pragma unroll
            for (int mt = 0; mt < 2; mt++) {
                int er = (ehalf * 2 + mt) * 16 + g;
                float4 t0 = *(const float4*)&sm[STMP + er * 132 + j * 4];
                float4 t1 = *(const float4*)&sm[STMP + (er + 8) * 132 + j * 4];
                float r00 = ahh[mt][0] + ahl[mt][0] + alh[mt][0];
                float r01 = ahh[mt][1] + ahl[mt][1] + alh[mt][1];
                float r10 = ahh[mt][2] + ahl[mt][2] + alh[mt][2];
                float r11 = ahh[mt][3] + ahl[mt][3] + alh[mt][3];
                cp[mt][0]  += r00 * t0.x; cp[mt][1]  += r00 * t0.y;
                cp[mt][2]  += r00 * t0.z; cp[mt][3]  += r00 * t0.w;
                cp[mt][4]  += r01 * t0.x; cp[mt][5]  += r01 * t0.y;
                cp[mt][6]  += r01 * t0.z; cp[mt][7]  += r01 * t0.w;
                cp[mt][8]  += r10 * t1.x; cp[mt][9]  += r10 * t1.y;
                cp[mt][10] += r10 * t1.z; cp[mt][11] += r10 * t1.w;
                cp[mt][12] += r11 * t1.x; cp[mt][13] += r11 * t1.y;
                cp[mt][14] += r11 * t1.z; cp[mt][15] += r11 * t1.w;
            }
        }
        __syncthreads();  // staging region -> SCONV
#pragma unroll
        for (int mt = 0; mt < 2; mt++) {
            int er = (ehalf * 2 + mt) * 16 + g;
            *(float4*)&sm[SCONV + er * 100 + i0 * 4]        = *(float4*)&cp[mt][0];
            *(float4*)&sm[SCONV + er * 100 + (i0 + 1) * 4]  = *(float4*)&cp[mt][4];
            *(float4*)&sm[SCONV + (er + 8) * 100 + i0 * 4]       = *(float4*)&cp[mt][8];
            *(float4*)&sm[SCONV + (er + 8) * 100 + (i0 + 1) * 4] = *(float4*)&cp[mt][12];
        }
    }
    __syncthreads();

    // ---- phase C: scores + v ----
    for (int idx = t; idx < 256; idx += 192) {
        int el2 = idx >> 2, hh = idx & 3;
        float sc = 0.0f;
#pragma unroll
        for (int x = 0; x < 8; x++) {
            int m = 2 * hh + (x >> 2), d = x & 3;
            sc += sm[SCONV + el2 * 100 + m * 4 + d] *
                  sm[SCONV + el2 * 100 + (8 + m) * 4 + d];
        }
        sc *= 0.17677669529663687f;          // 32^-0.5
        sc = sc >= 0.0f ? sc : 0.2f * sc;    // LeakyReLU(0.2)
        int ee = e0 + el2;
        if (ee < E) {
            scoresG[ee * 4 + hh] = sc;
            atomicMaxF(&smaxG[dst[ee] * 4 + hh], sc);
        }
    }
    for (int idx = t; idx < 512; idx += 192) {
        int el = idx >> 3, q = idx & 7;
        int ee = e0 + el;
        if (ee < E)
            *(float4*)&vG[(size_t)ee * 32 + q * 4] =
                *(const float4*)&sm[SCONV + el * 100 + 64 + q * 4];
    }
}

// ---------------- softmax accumulate ----------------
__global__ void attn_kernel(const int* __restrict__ dst, int E) {
    int idx = blockIdx.x * blockDim.x + threadIdx.x;
    if (idx >= E * 4) return;
    int e = idx >> 2, h = idx & 3;
    int dn = dst[e];
    float ex = expf(scoresG[idx] - smaxG[dn * 4 + h]);
    const float4* vp = (const float4*)(vG + (size_t)e * 32 + h * 8);
    float4 va = vp[0], vb = vp[1];
    float* p = accG + (size_t)dn * 48 + h * 12;
    redAdd4(p,     ex * va.x, ex * va.y, ex * va.z, ex * va.w);
    redAdd4(p + 4, ex * vb.x, ex * vb.y, ex * vb.z, ex * vb.w);
    redAdd4(p + 8, ex, 0.f, 0.f, 0.f);
}

// ---------------- node output ----------------
__global__ void out_kernel(const float* __restrict__ proj_w, float* __restrict__ out, int N) {
    int idx = blockIdx.x * blockDim.x + threadIdx.x;
    if (idx >= N * 4) return;
    int n = idx >> 2, d = idx & 3;
    float den[4];
#pragma unroll
    for (int h = 0; h < 4; h++) den[h] = accG[(size_t)n * 48 + h * 12 + 8];
    float oc[8];
#pragma unroll
    for (int m2 = 0; m2 < 8; m2++) {
        int h = m2 >> 1;
        float dd = den[h];
        float nm = accG[(size_t)n * 48 + h * 12 + (m2 & 1) * 4 + d];
        oc[m2] = dd > 0.0f ? nm / dd : 0.0f;
    }
    int ro = (d == 0) ? 0 : 8;                 // ix2 = [0,1,1,1]
#pragma unroll
    for (int m = 0; m < 8; m++) {
        float r = 0.0f;
#pragma unroll
        for (int m2 = 0; m2 < 8; m2++) r += proj_w[(ro + m) * 8 + m2] * oc[m2];
        out[(size_t)n * 32 + m * 4 + d] = r;
    }
}

// ---------------- launcher ----------------
extern "C" void kernel_launch(void* const* d_in, const int* in_sizes, int n_in,
                              void* d_out, int out_size) {
    const int*   src        = (const int*)d_in[0];
    const int*   dst        = (const int*)d_in[1];
    const float* basis      = (const float*)d_in[2];
    const float* features   = (const float*)d_in[3];
    const float* edge_feats = (const float*)d_in[4];
    const float* w1         = (const float*)d_in[5];
    const float* b1         = (const float*)d_in[6];
    const float* w2         = (const float*)d_in[7];
    const float* b2         = (const float*)d_in[8];
    const float* ln_w       = (const float*)d_in[9];
    const float* ln_b       = (const float*)d_in[10];
    const float* proj_w     = (const float*)d_in[11];
    float* out = (float*)d_out;

    int E = in_sizes[0];
    int N = in_sizes[3] / 32;

    init_kernel<<<(N * 48 + 255) / 256, 256>>>(N);
    prep_w2_kernel<<<96, 256>>>(w2);
    node_ln_kernel<<<(N + 127) / 128, 128>>>(features, ln_w, ln_b, N);

    size_t smbytes = STOT * sizeof(float);
    cudaFuncSetAttribute(edge_kernel, cudaFuncAttributeMaxDynamicSharedMemorySize, (int)smbytes);
    edge_kernel<<<(E + 63) / 64, 192, smbytes>>>(src, dst, basis, edge_feats,
                                                 w1, b1, b2, E);

    attn_kernel<<<(E * 4 + 255) / 256, 256>>>(dst, E);
    out_kernel<<<(N * 4 + 255) / 256, 256>>>(proj_w, out, N);
}

// round 4
// speedup vs baseline: 4.8024x; 1.1886x over previous
#include <cuda_runtime.h>
#include <cuda_bf16.h>
#include <math_constants.h>

#define NN 40000
#define NE 320000

// ---------------- scratch (device globals; no allocation allowed) ----------------
__device__ float fG[NN * 32];
__device__ float scoresG[NE * 4];
__device__ float vG[NE * 32];
__device__ float smaxG[NN * 4];
__device__ float accG[NN * 48];   // per (n,h): [0..7]=num, [8]=den, pad
// w2 split bf16, j-major fragment layout: uint4 = (hi_b0, hi_b1, lo_b0, lo_b1)
// ntile t = j*3 + ig (i = ig*8 + g); index = ((t*4 + ks)*32 + lane)
__device__ uint4 w2pG[96 * 4 * 32];
// w1 split bf16 fragment layout: index = ((nt*2 + ks)*32 + lane)
__device__ uint4 w1pG[16 * 32];

__device__ __forceinline__ void atomicMaxF(float* a, float v) {
    if (v == 0.0f) v = 0.0f;
    if (v >= 0.0f) atomicMax((int*)a, __float_as_int(v));
    else           atomicMin((unsigned int*)a, __float_as_uint(v));
}

__device__ __forceinline__ void redAdd4(float* p, float a, float b, float c, float d) {
    asm volatile("red.global.add.v4.f32 [%0], {%1,%2,%3,%4};"
                 :: "l"(p), "f"(a), "f"(b), "f"(c), "f"(d) : "memory");
}

__device__ __forceinline__ void mma_bf16(float* c, const unsigned* a, unsigned b0, unsigned b1) {
    asm volatile("mma.sync.aligned.m16n8k16.row.col.f32.bf16.bf16.f32 "
                 "{%0,%1,%2,%3}, {%4,%5,%6,%7}, {%8,%9}, {%0,%1,%2,%3};\n"
                 : "+f"(c[0]), "+f"(c[1]), "+f"(c[2]), "+f"(c[3])
                 : "r"(a[0]), "r"(a[1]), "r"(a[2]), "r"(a[3]), "r"(b0), "r"(b1));
}

// packed fp32x2 helpers (sm_100a FFMA2 path)
__device__ __forceinline__ unsigned long long packf2(float x, float y) {
    unsigned long long r;
    asm("mov.b64 %0, {%1,%2};" : "=l"(r) : "f"(x), "f"(y));
    return r;
}
__device__ __forceinline__ float2 unpackf2(unsigned long long v) {
    float2 r;
    asm("mov.b64 {%0,%1}, %2;" : "=f"(r.x), "=f"(r.y) : "l"(v));
    return r;
}
__device__ __forceinline__ void ffma2(unsigned long long& d, unsigned long long a, unsigned long long b) {
    asm("fma.rn.f32x2 %0, %1, %2, %0;" : "+l"(d) : "l"(a), "l"(b));
}

__device__ __forceinline__ void splitpack(float a, float b, unsigned& hi, unsigned& lo) {
    __nv_bfloat16 ha = __float2bfloat16_rn(a), hb = __float2bfloat16_rn(b);
    __nv_bfloat16 la = __float2bfloat16_rn(a - __bfloat162float(ha));
    __nv_bfloat16 lb = __float2bfloat16_rn(b - __bfloat162float(hb));
    hi = ((unsigned)__bfloat16_as_ushort(hb) << 16) | (unsigned)__bfloat16_as_ushort(ha);
    lo = ((unsigned)__bfloat16_as_ushort(lb) << 16) | (unsigned)__bfloat16_as_ushort(la);
}

// ---------------- init scratch ----------------
__global__ void init_kernel(int N) {
    int i = blockIdx.x * blockDim.x + threadIdx.x;
    if (i < N * 4) smaxG[i] = -CUDART_INF_F;
    if (i < N * 48) accG[i] = 0.0f;
}

// ---------------- prep: w2 -> split bf16, j-major fragment layout ----------------
__global__ void prep_w2_kernel(const float* __restrict__ w2) {
    int idx = blockIdx.x * 256 + threadIdx.x;
    if (idx >= 768 * 32) return;
    int o = idx >> 5, kp = idx & 31;             // o: w2 row, kp: k-pair
    unsigned hiu, lou;
    splitpack(w2[o * 64 + 2 * kp], w2[o * 64 + 2 * kp + 1], hiu, lou);
    int i = o >> 5, j = o & 31;                  // o = i*32 + j
    int tt = j * 3 + (i >> 3);                   // j-major ntile
    int g = i & 7;
    int ks = kp >> 3;
    int tq = kp & 3;
    int half = (kp >> 2) & 1;                    // b0 vs b1
    int frag = (tt * 4 + ks) * 32 + g * 4 + tq;
    ((unsigned*)w2pG)[frag * 4 + half]     = hiu;
    ((unsigned*)w2pG)[frag * 4 + 2 + half] = lou;
}

// ---------------- prep: w1 -> split bf16 B-fragment layout ----------------
__global__ void prep_w1_kernel(const float* __restrict__ w1) {
    int idx = blockIdx.x * 256 + threadIdx.x;
    if (idx >= 512) return;
    int lane = idx & 31, ksnt = idx >> 5;        // 0..15
    int ks = ksnt & 1, nt = ksnt >> 1;
    int g = lane >> 2, tq = lane & 3;
    int j = nt * 8 + g;
    int k0 = ks * 16 + 2 * tq;
    unsigned h0, l0, h1, l1;
    splitpack(w1[j * 32 + k0],     w1[j * 32 + k0 + 1],     h0, l0);
    splitpack(w1[j * 32 + k0 + 8], w1[j * 32 + k0 + 8 + 1], h1, l1);
    w1pG[(nt * 2 + ks) * 32 + lane] = make_uint4(h0, h1, l0, l1);
}

// ---------------- node-wise equivariant layer norm ----------------
__global__ void node_ln_kernel(const float* __restrict__ features,
                               const float* __restrict__ ln_w,
                               const float* __restrict__ ln_b, int N) {
    int n = blockIdx.x * blockDim.x + threadIdx.x;
    if (n >= N) return;
    float f[32];
    const float4* fp = (const float4*)(features + (size_t)n * 32);
#pragma unroll
    for (int q = 0; q < 8; q++) {
        float4 v = fp[q];
        f[q * 4 + 0] = v.x; f[q * 4 + 1] = v.y; f[q * 4 + 2] = v.z; f[q * 4 + 3] = v.w;
    }
    float nf[16];
#pragma unroll
    for (int m = 0; m < 8; m++) {
        nf[2 * m]     = sqrtf(f[m * 4] * f[m * 4]);
        nf[2 * m + 1] = sqrtf(f[m * 4 + 1] * f[m * 4 + 1] +
                              f[m * 4 + 2] * f[m * 4 + 2] +
                              f[m * 4 + 3] * f[m * 4 + 3]);
    }
    float ratio[16];
#pragma unroll
    for (int g = 0; g < 2; g++) {
        float mu = 0.0f;
#pragma unroll
        for (int b = 0; b < 8; b++) mu += nf[8 * g + b];
        mu *= 0.125f;
        float var = 0.0f;
#pragma unroll
        for (int b = 0; b < 8; b++) { float d = nf[8 * g + b] - mu; var += d * d; }
        var *= 0.125f;
        float rs = rsqrtf(var + 1e-5f);
#pragma unroll
        for (int b = 0; b < 8; b++) {
            float l = (nf[8 * g + b] - mu) * rs * ln_w[b] + ln_b[b];
            l = fmaxf(l, 0.0f);
            ratio[8 * g + b] = l / (nf[8 * g + b] + 1e-8f);
        }
    }
    float4* op = (float4*)(fG + (size_t)n * 32);
#pragma unroll
    for (int m = 0; m < 8; m++) {
        float4 v;
        v.x = f[m * 4 + 0] * ratio[2 * m];
        v.y = f[m * 4 + 1] * ratio[2 * m + 1];
        v.z = f[m * 4 + 2] * ratio[2 * m + 1];
        v.w = f[m * 4 + 3] * ratio[2 * m + 1];
        op[m] = v;
    }
}

// ---------------- fused per-edge kernel: 64 edges / 192 threads ----------------
// smem layout (float/uint indices)
#define SB2   0       // 768
#define STMP  768     // 64*132 -> 9216
#define SH2H  9216    // 64*36 uints -> 11520
#define SH2L  11520   // -> 13824
#define SSRC  13824   // 64 -> 13888
#define SSTG  13888
#define SEF   (SSTG)          // 64*32
#define SFU   (SSTG + 2048)   // 64*32
#define SBAS  (SSTG + 4096)   // 64*64
#define SCONV (SSTG)          // 64*100 = 6400 (staging dead by then)
#define STOT  22080           // 88320 bytes

__global__ __launch_bounds__(192, 2)
void edge_kernel(const int* __restrict__ src, const int* __restrict__ dst,
                 const float* __restrict__ basis, const float* __restrict__ edge_feats,
                 const float* __restrict__ b1, const float* __restrict__ b2, int E) {
    extern __shared__ float sm[];
    unsigned* smu = (unsigned*)sm;
    int t = threadIdx.x;
    int e0 = blockIdx.x * 64;
    int w = t >> 5, lane = t & 31, g = lane >> 2, tq = lane & 3;

    // ---- stage b2, src, then per-edge inputs ----
    if (t < 64) {
        int ee = e0 + t;
        ((int*)&sm[SSRC])[t] = __ldg(src + (ee < E ? ee : E - 1));
    }
    for (int idx = t; idx < 768; idx += 192) sm[SB2 + idx] = b2[idx];
    __syncthreads();

    for (int idx = t; idx < 512; idx += 192) {
        int el = idx >> 3, q = idx & 7;
        int ee = e0 + el; int ec = ee < E ? ee : E - 1;
        *(float4*)&sm[SEF + el * 32 + q * 4] =
            __ldg((const float4*)edge_feats + (size_t)ec * 8 + q);
        int s = ((const int*)&sm[SSRC])[el];
        *(float4*)&sm[SFU + el * 32 + q * 4] = ((const float4*)fG)[(size_t)s * 8 + q];
    }
    for (int idx = t; idx < 1024; idx += 192) {
        int el = idx >> 4, q = idx & 15;
        int ee = e0 + el; int ec = ee < E ? ee : E - 1;
        *(float4*)&sm[SBAS + el * 64 + q * 4] =
            __ldg((const float4*)basis + (size_t)ec * 16 + q);
    }
    __syncthreads();

    // ---- phase A1: tmp = fU x basis (all 192 threads) ----
    for (int idx = t; idx < 2048; idx += 192) {
        int el = idx >> 5, j = idx & 31;
        int m = j >> 2, pp = j & 3;
        float o0 = 0.f, o1 = 0.f, o2 = 0.f, o3 = 0.f;
#pragma unroll
        for (int dd = 0; dd < 4; dd++) {
            float fv = sm[SFU + el * 32 + m * 4 + dd];
            o0 += fv * sm[SBAS + el * 64 + dd * 16 + pp * 4 + 0];
            o1 += fv * sm[SBAS + el * 64 + dd * 16 + pp * 4 + 1];
            o2 += fv * sm[SBAS + el * 64 + dd * 16 + pp * 4 + 2];
            o3 += fv * sm[SBAS + el * 64 + dd * 16 + pp * 4 + 3];
        }
        *(float4*)&sm[STMP + el * 132 + j * 4] = make_float4(o0, o1, o2, o3);
    }

    // ---- phase A2: h = relu(ef@w1^T + b1) via split-bf16 MMA ----
    {
        int cur_mt = -1;
        unsigned eAh[2][4], eAl[2][4];
#pragma unroll
        for (int it = 0; it < 6; it++) {
            int p = w + it * 6;                   // (mt, nt) pair index, 32 total
            if (p < 32) {
                int mt = p >> 3, nt = p & 7;
                if (mt != cur_mt) {
                    cur_mt = mt;
#pragma unroll
                    for (int ks = 0; ks < 2; ks++) {
                        float2 x0 = *(const float2*)&sm[SEF + (mt * 16 + g) * 32 + ks * 16 + 2 * tq];
                        float2 x1 = *(const float2*)&sm[SEF + (mt * 16 + g + 8) * 32 + ks * 16 + 2 * tq];
                        float2 x2 = *(const float2*)&sm[SEF + (mt * 16 + g) * 32 + ks * 16 + 8 + 2 * tq];
                        float2 x3 = *(const float2*)&sm[SEF + (mt * 16 + g + 8) * 32 + ks * 16 + 8 + 2 * tq];
                        splitpack(x0.x, x0.y, eAh[ks][0], eAl[ks][0]);
                        splitpack(x1.x, x1.y, eAh[ks][1], eAl[ks][1]);
                        splitpack(x2.x, x2.y, eAh[ks][2], eAl[ks][2]);
                        splitpack(x3.x, x3.y, eAh[ks][3], eAl[ks][3]);
                    }
                }
                float2 bb = __ldg((const float2*)(b1 + nt * 8 + 2 * tq));
                float acc[4] = {bb.x, bb.y, bb.x, bb.y};
#pragma unroll
                for (int ks = 0; ks < 2; ks++) {
                    uint4 bv = __ldg(w1pG + (nt * 2 + ks) * 32 + lane);
                    mma_bf16(acc, eAh[ks], bv.x, bv.y);
                    mma_bf16(acc, eAh[ks], bv.z, bv.w);
                    mma_bf16(acc, eAl[ks], bv.x, bv.y);
                }
                int jp = nt * 4 + tq;
                int r0 = mt * 16 + g;
                unsigned h01, l01, h23, l23;
                splitpack(fmaxf(acc[0], 0.f), fmaxf(acc[1], 0.f), h01, l01);
                splitpack(fmaxf(acc[2], 0.f), fmaxf(acc[3], 0.f), h23, l23);
                smu[SH2H + r0 * 36 + jp] = h01;
                smu[SH2L + r0 * 36 + jp] = l01;
                smu[SH2H + (r0 + 8) * 36 + jp] = h23;
                smu[SH2L + (r0 + 8) * 36 + jp] = l23;
            }
        }
    }
    __syncthreads();

    // ---- phase B: rw GEMM (split bf16, pipelined) + fused j-local contraction ----
    {
        int ig = w % 3, ehalf = w / 3;
        int i0 = ig * 8 + 2 * tq;

        unsigned Ah[2][4][4], Al[2][4][4];
#pragma unroll
        for (int mt = 0; mt < 2; mt++) {
            int r0 = (ehalf * 2 + mt) * 16 + g;
#pragma unroll
            for (int ks = 0; ks < 4; ks++) {
                Ah[mt][ks][0] = smu[SH2H + r0 * 36 + ks * 8 + tq];
                Ah[mt][ks][1] = smu[SH2H + (r0 + 8) * 36 + ks * 8 + tq];
                Ah[mt][ks][2] = smu[SH2H + r0 * 36 + ks * 8 + 4 + tq];
                Ah[mt][ks][3] = smu[SH2H + (r0 + 8) * 36 + ks * 8 + 4 + tq];
                Al[mt][ks][0] = smu[SH2L + r0 * 36 + ks * 8 + tq];
                Al[mt][ks][1] = smu[SH2L + (r0 + 8) * 36 + ks * 8 + tq];
                Al[mt][ks][2] = smu[SH2L + r0 * 36 + ks * 8 + 4 + tq];
                Al[mt][ks][3] = smu[SH2L + (r0 + 8) * 36 + ks * 8 + 4 + tq];
            }
        }

        unsigned long long cp[2][8];
#pragma unroll
        for (int mt = 0; mt < 2; mt++)
#pragma unroll
            for (int x = 0; x < 8; x++) cp[mt][x] = 0ull;

        const uint4* wb = w2pG + lane;
        uint4 bv[4];
#pragma unroll
        for (int ks = 0; ks < 4; ks++) bv[ks] = __ldg(wb + (ig * 4 + ks) * 32);

#pragma unroll 1
        for (int j = 0; j < 32; j++) {
            int jn = (j < 31) ? j + 1 : 31;
            uint4 nbv[4];
#pragma unroll
            for (int ks = 0; ks < 4; ks++)
                nbv[ks] = __ldg(wb + ((jn * 3 + ig) * 4 + ks) * 32);

            float bz0 = sm[SB2 + i0 * 32 + j];
            float bz1 = sm[SB2 + (i0 + 1) * 32 + j];
            float mn[2][4], cr[2][4];
#pragma unroll
            for (int mt = 0; mt < 2; mt++) {
                mn[mt][0] = bz0; mn[mt][1] = bz1; mn[mt][2] = bz0; mn[mt][3] = bz1;
                cr[mt][0] = cr[mt][1] = cr[mt][2] = cr[mt][3] = 0.f;
            }
#pragma unroll
            for (int ks = 0; ks < 4; ks++)
#pragma unroll
                for (int mt = 0; mt < 2; mt++) {
                    mma_bf16(mn[mt], Ah[mt][ks], bv[ks].x, bv[ks].y);
                    mma_bf16(cr[mt], Ah[mt][ks], bv[ks].z, bv[ks].w);
                    mma_bf16(cr[mt], Al[mt][ks], bv[ks].x, bv[ks].y);
                }
#pragma unroll
            for (int mt = 0; mt < 2; mt++) {
                int er = (ehalf * 2 + mt) * 16 + g;
                float4 t0 = *(const float4*)&sm[STMP + er * 132 + j * 4];
                float4 t1 = *(const float4*)&sm[STMP + (er + 8) * 132 + j * 4];
                float r00 = mn[mt][0] + cr[mt][0], r01 = mn[mt][1] + cr[mt][1];
                float r10 = mn[mt][2] + cr[mt][2], r11 = mn[mt][3] + cr[mt][3];
                unsigned long long ta = packf2(t0.x, t0.y), tb = packf2(t0.z, t0.w);
                unsigned long long tc = packf2(t1.x, t1.y), td = packf2(t1.z, t1.w);
                unsigned long long rp;
                rp = packf2(r00, r00); ffma2(cp[mt][0], rp, ta); ffma2(cp[mt][1], rp, tb);
                rp = packf2(r01, r01); ffma2(cp[mt][2], rp, ta); ffma2(cp[mt][3], rp, tb);
                rp = packf2(r10, r10); ffma2(cp[mt][4], rp, tc); ffma2(cp[mt][5], rp, td);
                rp = packf2(r11, r11); ffma2(cp[mt][6], rp, tc); ffma2(cp[mt][7], rp, td);
            }
#pragma unroll
            for (int ks = 0; ks < 4; ks++) bv[ks] = nbv[ks];
        }

        // write conv (staging region is dead; SCONV overlaps it)
#pragma unroll
        for (int mt = 0; mt < 2; mt++) {
            int er = (ehalf * 2 + mt) * 16 + g;
            float2 a0 = unpackf2(cp[mt][0]), a1 = unpackf2(cp[mt][1]);
            float2 a2 = unpackf2(cp[mt][2]), a3 = unpackf2(cp[mt][3]);
            float2 a4 = unpackf2(cp[mt][4]), a5 = unpackf2(cp[mt][5]);
            float2 a6 = unpackf2(cp[mt][6]), a7 = unpackf2(cp[mt][7]);
            *(float4*)&sm[SCONV + er * 100 + i0 * 4]             = make_float4(a0.x, a0.y, a1.x, a1.y);
            *(float4*)&sm[SCONV + er * 100 + (i0 + 1) * 4]       = make_float4(a2.x, a2.y, a3.x, a3.y);
            *(float4*)&sm[SCONV + (er + 8) * 100 + i0 * 4]       = make_float4(a4.x, a4.y, a5.x, a5.y);
            *(float4*)&sm[SCONV + (er + 8) * 100 + (i0 + 1) * 4] = make_float4(a6.x, a6.y, a7.x, a7.y);
        }
    }
    __syncthreads();

    // ---- phase C: scores + v ----
    for (int idx = t; idx < 256; idx += 192) {
        int el2 = idx >> 2, hh = idx & 3;
        float sc = 0.0f;
#pragma unroll
        for (int x = 0; x < 8; x++) {
            int m = 2 * hh + (x >> 2), d = x & 3;
            sc += sm[SCONV + el2 * 100 + m * 4 + d] *
                  sm[SCONV + el2 * 100 + (8 + m) * 4 + d];
        }
        sc *= 0.17677669529663687f;          // 32^-0.5
        sc = sc >= 0.0f ? sc : 0.2f * sc;    // LeakyReLU(0.2)
        int ee = e0 + el2;
        if (ee < E) {
            scoresG[ee * 4 + hh] = sc;
            atomicMaxF(&smaxG[dst[ee] * 4 + hh], sc);
        }
    }
    for (int idx = t; idx < 512; idx += 192) {
        int el = idx >> 3, q = idx & 7;
        int ee = e0 + el;
        if (ee < E)
            *(float4*)&vG[(size_t)ee * 32 + q * 4] =
                *(const float4*)&sm[SCONV + el * 100 + 64 + q * 4];
    }
}

// ---------------- softmax accumulate ----------------
__global__ void attn_kernel(const int* __restrict__ dst, int E) {
    int idx = blockIdx.x * blockDim.x + threadIdx.x;
    if (idx >= E * 4) return;
    int e = idx >> 2, h = idx & 3;
    int dn = dst[e];
    float ex = expf(scoresG[idx] - smaxG[dn * 4 + h]);
    const float4* vp = (const float4*)(vG + (size_t)e * 32 + h * 8);
    float4 va = vp[0], vb = vp[1];
    float* p = accG + (size_t)dn * 48 + h * 12;
    redAdd4(p,     ex * va.x, ex * va.y, ex * va.z, ex * va.w);
    redAdd4(p + 4, ex * vb.x, ex * vb.y, ex * vb.z, ex * vb.w);
    redAdd4(p + 8, ex, 0.f, 0.f, 0.f);
}

// ---------------- node output ----------------
__global__ void out_kernel(const float* __restrict__ proj_w, float* __restrict__ out, int N) {
    int idx = blockIdx.x * blockDim.x + threadIdx.x;
    if (idx >= N * 4) return;
    int n = idx >> 2, d = idx & 3;
    float den[4];
#pragma unroll
    for (int h = 0; h < 4; h++) den[h] = accG[(size_t)n * 48 + h * 12 + 8];
    float oc[8];
#pragma unroll
    for (int m2 = 0; m2 < 8; m2++) {
        int h = m2 >> 1;
        float dd = den[h];
        float nm = accG[(size_t)n * 48 + h * 12 + (m2 & 1) * 4 + d];
        oc[m2] = dd > 0.0f ? nm / dd : 0.0f;
    }
    int ro = (d == 0) ? 0 : 8;                 // ix2 = [0,1,1,1]
#pragma unroll
    for (int m = 0; m < 8; m++) {
        float r = 0.0f;
#pragma unroll
        for (int m2 = 0; m2 < 8; m2++) r += proj_w[(ro + m) * 8 + m2] * oc[m2];
        out[(size_t)n * 32 + m * 4 + d] = r;
    }
}

// ---------------- launcher ----------------
extern "C" void kernel_launch(void* const* d_in, const int* in_sizes, int n_in,
                              void* d_out, int out_size) {
    const int*   src        = (const int*)d_in[0];
    const int*   dst        = (const int*)d_in[1];
    const float* basis      = (const float*)d_in[2];
    const float* features   = (const float*)d_in[3];
    const float* edge_feats = (const float*)d_in[4];
    const float* w1         = (const float*)d_in[5];
    const float* b1         = (const float*)d_in[6];
    const float* w2         = (const float*)d_in[7];
    const float* b2         = (const float*)d_in[8];
    const float* ln_w       = (const float*)d_in[9];
    const float* ln_b       = (const float*)d_in[10];
    const float* proj_w     = (const float*)d_in[11];
    float* out = (float*)d_out;

    int E = in_sizes[0];
    int N = in_sizes[3] / 32;

    init_kernel<<<(N * 48 + 255) / 256, 256>>>(N);
    prep_w2_kernel<<<96, 256>>>(w2);
    prep_w1_kernel<<<2, 256>>>(w1);
    node_ln_kernel<<<(N + 127) / 128, 128>>>(features, ln_w, ln_b, N);

    size_t smbytes = STOT * sizeof(float);
    cudaFuncSetAttribute(edge_kernel, cudaFuncAttributeMaxDynamicSharedMemorySize, (int)smbytes);
    edge_kernel<<<(E + 63) / 64, 192, smbytes>>>(src, dst, basis, edge_feats, b1, b2, E);

    attn_kernel<<<(E * 4 + 255) / 256, 256>>>(dst, E);
    out_kernel<<<(N * 4 + 255) / 256, 256>>>(proj_w, out, N);
}

// round 5
// speedup vs baseline: 5.1603x; 1.0745x over previous
#include <cuda_runtime.h>
#include <cuda_bf16.h>
#include <math_constants.h>

#define NN 40000
#define NE 320000

// ---------------- scratch (device globals; no allocation allowed) ----------------
__device__ float fG[NN * 32];
__device__ float scoresG[NE * 4];
__device__ float vG[NE * 32];
__device__ float smaxG[NN * 4];
__device__ float accG[NN * 48];   // per (n,h): [0..7]=num, [8]=den, pad
// w2 split bf16, j-major fragment layout: uint4 = (hi_b0, hi_b1, lo_b0, lo_b1)
// ntile t = j*3 + ig (i = ig*8 + g); index = ((t*4 + ks)*32 + lane)
__device__ uint4 w2pG[96 * 4 * 32];
// w1 split bf16 fragment layout: index = ((nt*2 + ks)*32 + lane)
__device__ uint4 w1pG[16 * 32];

__device__ __forceinline__ void atomicMaxF(float* a, float v) {
    if (v == 0.0f) v = 0.0f;
    if (v >= 0.0f) atomicMax((int*)a, __float_as_int(v));
    else           atomicMin((unsigned int*)a, __float_as_uint(v));
}

__device__ __forceinline__ void redAdd4(float* p, float a, float b, float c, float d) {
    asm volatile("red.global.add.v4.f32 [%0], {%1,%2,%3,%4};"
                 :: "l"(p), "f"(a), "f"(b), "f"(c), "f"(d) : "memory");
}

__device__ __forceinline__ void mma_bf16(float* c, const unsigned* a, unsigned b0, unsigned b1) {
    asm volatile("mma.sync.aligned.m16n8k16.row.col.f32.bf16.bf16.f32 "
                 "{%0,%1,%2,%3}, {%4,%5,%6,%7}, {%8,%9}, {%0,%1,%2,%3};\n"
                 : "+f"(c[0]), "+f"(c[1]), "+f"(c[2]), "+f"(c[3])
                 : "r"(a[0]), "r"(a[1]), "r"(a[2]), "r"(a[3]), "r"(b0), "r"(b1));
}

// packed fp32x2 helpers (sm_100a FFMA2 path)
__device__ __forceinline__ unsigned long long packf2(float x, float y) {
    unsigned long long r;
    asm("mov.b64 %0, {%1,%2};" : "=l"(r) : "f"(x), "f"(y));
    return r;
}
__device__ __forceinline__ float2 unpackf2(unsigned long long v) {
    float2 r;
    asm("mov.b64 {%0,%1}, %2;" : "=f"(r.x), "=f"(r.y) : "l"(v));
    return r;
}
__device__ __forceinline__ void ffma2(unsigned long long& d, unsigned long long a, unsigned long long b) {
    asm("fma.rn.f32x2 %0, %1, %2, %0;" : "+l"(d) : "l"(a), "l"(b));
}

__device__ __forceinline__ void splitpack(float a, float b, unsigned& hi, unsigned& lo) {
    __nv_bfloat16 ha = __float2bfloat16_rn(a), hb = __float2bfloat16_rn(b);
    __nv_bfloat16 la = __float2bfloat16_rn(a - __bfloat162float(ha));
    __nv_bfloat16 lb = __float2bfloat16_rn(b - __bfloat162float(hb));
    hi = ((unsigned)__bfloat16_as_ushort(hb) << 16) | (unsigned)__bfloat16_as_ushort(ha);
    lo = ((unsigned)__bfloat16_as_ushort(lb) << 16) | (unsigned)__bfloat16_as_ushort(la);
}

// ---------------- init scratch ----------------
__global__ void init_kernel(int N) {
    int i = blockIdx.x * blockDim.x + threadIdx.x;
    if (i < N * 4) smaxG[i] = -CUDART_INF_F;
    if (i < N * 48) accG[i] = 0.0f;
}

// ---------------- prep: w2 -> split bf16, j-major fragment layout ----------------
__global__ void prep_w2_kernel(const float* __restrict__ w2) {
    int idx = blockIdx.x * 256 + threadIdx.x;
    if (idx >= 768 * 32) return;
    int o = idx >> 5, kp = idx & 31;             // o: w2 row, kp: k-pair
    unsigned hiu, lou;
    splitpack(w2[o * 64 + 2 * kp], w2[o * 64 + 2 * kp + 1], hiu, lou);
    int i = o >> 5, j = o & 31;                  // o = i*32 + j
    int tt = j * 3 + (i >> 3);                   // j-major ntile
    int g = i & 7;
    int ks = kp >> 3;
    int tq = kp & 3;
    int half = (kp >> 2) & 1;                    // b0 vs b1
    int frag = (tt * 4 + ks) * 32 + g * 4 + tq;
    ((unsigned*)w2pG)[frag * 4 + half]     = hiu;
    ((unsigned*)w2pG)[frag * 4 + 2 + half] = lou;
}

// ---------------- prep: w1 -> split bf16 B-fragment layout ----------------
__global__ void prep_w1_kernel(const float* __restrict__ w1) {
    int idx = blockIdx.x * 256 + threadIdx.x;
    if (idx >= 512) return;
    int lane = idx & 31, ksnt = idx >> 5;        // 0..15
    int ks = ksnt & 1, nt = ksnt >> 1;
    int g = lane >> 2, tq = lane & 3;
    int j = nt * 8 + g;
    int k0 = ks * 16 + 2 * tq;
    unsigned h0, l0, h1, l1;
    splitpack(w1[j * 32 + k0],     w1[j * 32 + k0 + 1],     h0, l0);
    splitpack(w1[j * 32 + k0 + 8], w1[j * 32 + k0 + 8 + 1], h1, l1);
    w1pG[(nt * 2 + ks) * 32 + lane] = make_uint4(h0, h1, l0, l1);
}

// ---------------- node-wise equivariant layer norm ----------------
__global__ void node_ln_kernel(const float* __restrict__ features,
                               const float* __restrict__ ln_w,
                               const float* __restrict__ ln_b, int N) {
    int n = blockIdx.x * blockDim.x + threadIdx.x;
    if (n >= N) return;
    float f[32];
    const float4* fp = (const float4*)(features + (size_t)n * 32);
#pragma unroll
    for (int q = 0; q < 8; q++) {
        float4 v = fp[q];
        f[q * 4 + 0] = v.x; f[q * 4 + 1] = v.y; f[q * 4 + 2] = v.z; f[q * 4 + 3] = v.w;
    }
    float nf[16];
#pragma unroll
    for (int m = 0; m < 8; m++) {
        nf[2 * m]     = sqrtf(f[m * 4] * f[m * 4]);
        nf[2 * m + 1] = sqrtf(f[m * 4 + 1] * f[m * 4 + 1] +
                              f[m * 4 + 2] * f[m * 4 + 2] +
                              f[m * 4 + 3] * f[m * 4 + 3]);
    }
    float ratio[16];
#pragma unroll
    for (int g = 0; g < 2; g++) {
        float mu = 0.0f;
#pragma unroll
        for (int b = 0; b < 8; b++) mu += nf[8 * g + b];
        mu *= 0.125f;
        float var = 0.0f;
#pragma unroll
        for (int b = 0; b < 8; b++) { float d = nf[8 * g + b] - mu; var += d * d; }
        var *= 0.125f;
        float rs = rsqrtf(var + 1e-5f);
#pragma unroll
        for (int b = 0; b < 8; b++) {
            float l = (nf[8 * g + b] - mu) * rs * ln_w[b] + ln_b[b];
            l = fmaxf(l, 0.0f);
            ratio[8 * g + b] = l / (nf[8 * g + b] + 1e-8f);
        }
    }
    float4* op = (float4*)(fG + (size_t)n * 32);
#pragma unroll
    for (int m = 0; m < 8; m++) {
        float4 v;
        v.x = f[m * 4 + 0] * ratio[2 * m];
        v.y = f[m * 4 + 1] * ratio[2 * m + 1];
        v.z = f[m * 4 + 2] * ratio[2 * m + 1];
        v.w = f[m * 4 + 3] * ratio[2 * m + 1];
        op[m] = v;
    }
}

// ---------------- fused per-edge kernel: 64 edges / 192 threads ----------------
// smem layout (float/uint indices)
#define SB2   0       // 768
#define STMP  768     // 64*132 -> 9216
#define SH2H  9216    // 64*36 uints -> 11520
#define SH2L  11520   // -> 13824
#define SSRC  13824   // 64 -> 13888
#define SSTG  13888
#define SEF   (SSTG)          // 64*32
#define SFU   (SSTG + 2048)   // 64*32
#define SBAS  (SSTG + 4096)   // 64*64
#define SCONV (SSTG)          // 64*68 = 4352 (k,q only; staging dead by then)
#define STOT  22080           // 88320 bytes

__global__ __launch_bounds__(192, 2)
void edge_kernel(const int* __restrict__ src, const int* __restrict__ dst,
                 const float* __restrict__ basis, const float* __restrict__ edge_feats,
                 const float* __restrict__ b1, const float* __restrict__ b2, int E) {
    extern __shared__ float sm[];
    unsigned* smu = (unsigned*)sm;
    int t = threadIdx.x;
    int e0 = blockIdx.x * 64;
    int w = t >> 5, lane = t & 31, g = lane >> 2, tq = lane & 3;

    // ---- stage b2, src, then per-edge inputs ----
    if (t < 64) {
        int ee = e0 + t;
        ((int*)&sm[SSRC])[t] = __ldg(src + (ee < E ? ee : E - 1));
    }
    for (int idx = t; idx < 768; idx += 192) sm[SB2 + idx] = b2[idx];
    __syncthreads();

    for (int idx = t; idx < 512; idx += 192) {
        int el = idx >> 3, q = idx & 7;
        int ee = e0 + el; int ec = ee < E ? ee : E - 1;
        *(float4*)&sm[SEF + el * 32 + q * 4] =
            __ldg((const float4*)edge_feats + (size_t)ec * 8 + q);
        int s = ((const int*)&sm[SSRC])[el];
        *(float4*)&sm[SFU + el * 32 + q * 4] = ((const float4*)fG)[(size_t)s * 8 + q];
    }
    for (int idx = t; idx < 1024; idx += 192) {
        int el = idx >> 4, q = idx & 15;
        int ee = e0 + el; int ec = ee < E ? ee : E - 1;
        *(float4*)&sm[SBAS + el * 64 + q * 4] =
            __ldg((const float4*)basis + (size_t)ec * 16 + q);
    }
    __syncthreads();

    // ---- phase A1: tmp = fU x basis (all 192 threads) ----
    for (int idx = t; idx < 2048; idx += 192) {
        int el = idx >> 5, j = idx & 31;
        int m = j >> 2, pp = j & 3;
        float o0 = 0.f, o1 = 0.f, o2 = 0.f, o3 = 0.f;
#pragma unroll
        for (int dd = 0; dd < 4; dd++) {
            float fv = sm[SFU + el * 32 + m * 4 + dd];
            o0 += fv * sm[SBAS + el * 64 + dd * 16 + pp * 4 + 0];
            o1 += fv * sm[SBAS + el * 64 + dd * 16 + pp * 4 + 1];
            o2 += fv * sm[SBAS + el * 64 + dd * 16 + pp * 4 + 2];
            o3 += fv * sm[SBAS + el * 64 + dd * 16 + pp * 4 + 3];
        }
        *(float4*)&sm[STMP + el * 132 + j * 4] = make_float4(o0, o1, o2, o3);
    }

    // ---- phase A2: h = relu(ef@w1^T + b1) via split-bf16 MMA ----
    {
        int cur_mt = -1;
        unsigned eAh[2][4], eAl[2][4];
#pragma unroll
        for (int it = 0; it < 6; it++) {
            int p = w + it * 6;                   // (mt, nt) pair index, 32 total
            if (p < 32) {
                int mt = p >> 3, nt = p & 7;
                if (mt != cur_mt) {
                    cur_mt = mt;
#pragma unroll
                    for (int ks = 0; ks < 2; ks++) {
                        float2 x0 = *(const float2*)&sm[SEF + (mt * 16 + g) * 32 + ks * 16 + 2 * tq];
                        float2 x1 = *(const float2*)&sm[SEF + (mt * 16 + g + 8) * 32 + ks * 16 + 2 * tq];
                        float2 x2 = *(const float2*)&sm[SEF + (mt * 16 + g) * 32 + ks * 16 + 8 + 2 * tq];
                        float2 x3 = *(const float2*)&sm[SEF + (mt * 16 + g + 8) * 32 + ks * 16 + 8 + 2 * tq];
                        splitpack(x0.x, x0.y, eAh[ks][0], eAl[ks][0]);
                        splitpack(x1.x, x1.y, eAh[ks][1], eAl[ks][1]);
                        splitpack(x2.x, x2.y, eAh[ks][2], eAl[ks][2]);
                        splitpack(x3.x, x3.y, eAh[ks][3], eAl[ks][3]);
                    }
                }
                float2 bb = __ldg((const float2*)(b1 + nt * 8 + 2 * tq));
                float acc[4] = {bb.x, bb.y, bb.x, bb.y};
#pragma unroll
                for (int ks = 0; ks < 2; ks++) {
                    uint4 bv = __ldg(w1pG + (nt * 2 + ks) * 32 + lane);
                    mma_bf16(acc, eAh[ks], bv.x, bv.y);
                    mma_bf16(acc, eAh[ks], bv.z, bv.w);
                    mma_bf16(acc, eAl[ks], bv.x, bv.y);
                }
                int jp = nt * 4 + tq;
                int r0 = mt * 16 + g;
                unsigned h01, l01, h23, l23;
                splitpack(fmaxf(acc[0], 0.f), fmaxf(acc[1], 0.f), h01, l01);
                splitpack(fmaxf(acc[2], 0.f), fmaxf(acc[3], 0.f), h23, l23);
                smu[SH2H + r0 * 36 + jp] = h01;
                smu[SH2L + r0 * 36 + jp] = l01;
                smu[SH2H + (r0 + 8) * 36 + jp] = h23;
                smu[SH2L + (r0 + 8) * 36 + jp] = l23;
            }
        }
    }
    __syncthreads();

    // ---- phase B: rw GEMM (split bf16, single-acc chains, pipelined) + fused contraction ----
    {
        int ig = w % 3, ehalf = w / 3;
        int i0 = ig * 8 + 2 * tq;

        unsigned Ah[2][4][4], Al[2][4][4];
#pragma unroll
        for (int mt = 0; mt < 2; mt++) {
            int r0 = (ehalf * 2 + mt) * 16 + g;
#pragma unroll
            for (int ks = 0; ks < 4; ks++) {
                Ah[mt][ks][0] = smu[SH2H + r0 * 36 + ks * 8 + tq];
                Ah[mt][ks][1] = smu[SH2H + (r0 + 8) * 36 + ks * 8 + tq];
                Ah[mt][ks][2] = smu[SH2H + r0 * 36 + ks * 8 + 4 + tq];
                Ah[mt][ks][3] = smu[SH2H + (r0 + 8) * 36 + ks * 8 + 4 + tq];
                Al[mt][ks][0] = smu[SH2L + r0 * 36 + ks * 8 + tq];
                Al[mt][ks][1] = smu[SH2L + (r0 + 8) * 36 + ks * 8 + tq];
                Al[mt][ks][2] = smu[SH2L + r0 * 36 + ks * 8 + 4 + tq];
                Al[mt][ks][3] = smu[SH2L + (r0 + 8) * 36 + ks * 8 + 4 + tq];
            }
        }

        unsigned long long cp[2][8];
#pragma unroll
        for (int mt = 0; mt < 2; mt++)
#pragma unroll
            for (int x = 0; x < 8; x++) cp[mt][x] = 0ull;

        const uint4* wb = w2pG + lane;
        uint4 bv[4];
#pragma unroll
        for (int ks = 0; ks < 4; ks++) bv[ks] = __ldg(wb + (ig * 4 + ks) * 32);

#pragma unroll 2
        for (int j = 0; j < 32; j++) {
            int jn = (j < 31) ? j + 1 : 31;
            uint4 nbv[4];
#pragma unroll
            for (int ks = 0; ks < 4; ks++)
                nbv[ks] = __ldg(wb + ((jn * 3 + ig) * 4 + ks) * 32);

            float bz0 = sm[SB2 + i0 * 32 + j];
            float bz1 = sm[SB2 + (i0 + 1) * 32 + j];
            float mn[2][4];
#pragma unroll
            for (int mt = 0; mt < 2; mt++) {
                mn[mt][0] = bz0; mn[mt][1] = bz1; mn[mt][2] = bz0; mn[mt][3] = bz1;
            }
            // all three split products accumulate into one chain (acc-dep HMMA = rt)
#pragma unroll
            for (int ks = 0; ks < 4; ks++)
#pragma unroll
                for (int mt = 0; mt < 2; mt++) {
                    mma_bf16(mn[mt], Ah[mt][ks], bv[ks].x, bv[ks].y);
                    mma_bf16(mn[mt], Ah[mt][ks], bv[ks].z, bv[ks].w);
                    mma_bf16(mn[mt], Al[mt][ks], bv[ks].x, bv[ks].y);
                }
#pragma unroll
            for (int mt = 0; mt < 2; mt++) {
                int er = (ehalf * 2 + mt) * 16 + g;
                float4 t0 = *(const float4*)&sm[STMP + er * 132 + j * 4];
                float4 t1 = *(const float4*)&sm[STMP + (er + 8) * 132 + j * 4];
                unsigned long long ta = packf2(t0.x, t0.y), tb = packf2(t0.z, t0.w);
                unsigned long long tc = packf2(t1.x, t1.y), td = packf2(t1.z, t1.w);
                unsigned long long rp;
                rp = packf2(mn[mt][0], mn[mt][0]); ffma2(cp[mt][0], rp, ta); ffma2(cp[mt][1], rp, tb);
                rp = packf2(mn[mt][1], mn[mt][1]); ffma2(cp[mt][2], rp, ta); ffma2(cp[mt][3], rp, tb);
                rp = packf2(mn[mt][2], mn[mt][2]); ffma2(cp[mt][4], rp, tc); ffma2(cp[mt][5], rp, td);
                rp = packf2(mn[mt][3], mn[mt][3]); ffma2(cp[mt][6], rp, tc); ffma2(cp[mt][7], rp, td);
            }
#pragma unroll
            for (int ks = 0; ks < 4; ks++) bv[ks] = nbv[ks];
        }

        // write conv: k,q (i<16) -> smem; v (i>=16, ig==2) -> gmem directly
        if (ig < 2) {
#pragma unroll
            for (int mt = 0; mt < 2; mt++) {
                int er = (ehalf * 2 + mt) * 16 + g;
                float2 a0 = unpackf2(cp[mt][0]), a1 = unpackf2(cp[mt][1]);
                float2 a2 = unpackf2(cp[mt][2]), a3 = unpackf2(cp[mt][3]);
                float2 a4 = unpackf2(cp[mt][4]), a5 = unpackf2(cp[mt][5]);
                float2 a6 = unpackf2(cp[mt][6]), a7 = unpackf2(cp[mt][7]);
                *(float4*)&sm[SCONV + er * 68 + i0 * 4]            = make_float4(a0.x, a0.y, a1.x, a1.y);
                *(float4*)&sm[SCONV + er * 68 + (i0 + 1) * 4]      = make_float4(a2.x, a2.y, a3.x, a3.y);
                *(float4*)&sm[SCONV + (er + 8) * 68 + i0 * 4]      = make_float4(a4.x, a4.y, a5.x, a5.y);
                *(float4*)&sm[SCONV + (er + 8) * 68 + (i0 + 1) * 4] = make_float4(a6.x, a6.y, a7.x, a7.y);
            }
        } else {
#pragma unroll
            for (int mt = 0; mt < 2; mt++) {
                int er = (ehalf * 2 + mt) * 16 + g;
                int v0 = (i0 - 16) * 4;
                float2 a0 = unpackf2(cp[mt][0]), a1 = unpackf2(cp[mt][1]);
                float2 a2 = unpackf2(cp[mt][2]), a3 = unpackf2(cp[mt][3]);
                float2 a4 = unpackf2(cp[mt][4]), a5 = unpackf2(cp[mt][5]);
                float2 a6 = unpackf2(cp[mt][6]), a7 = unpackf2(cp[mt][7]);
                if (e0 + er < E) {
                    *(float4*)&vG[(size_t)(e0 + er) * 32 + v0]     = make_float4(a0.x, a0.y, a1.x, a1.y);
                    *(float4*)&vG[(size_t)(e0 + er) * 32 + v0 + 4] = make_float4(a2.x, a2.y, a3.x, a3.y);
                }
                if (e0 + er + 8 < E) {
                    *(float4*)&vG[(size_t)(e0 + er + 8) * 32 + v0]     = make_float4(a4.x, a4.y, a5.x, a5.y);
                    *(float4*)&vG[(size_t)(e0 + er + 8) * 32 + v0 + 4] = make_float4(a6.x, a6.y, a7.x, a7.y);
                }
            }
        }
    }
    __syncthreads();

    // ---- phase C: scores ----
    for (int idx = t; idx < 256; idx += 192) {
        int el2 = idx >> 2, hh = idx & 3;
        float sc = 0.0f;
#pragma unroll
        for (int x = 0; x < 8; x++) {
            int m = 2 * hh + (x >> 2), d = x & 3;
            sc += sm[SCONV + el2 * 68 + m * 4 + d] *
                  sm[SCONV + el2 * 68 + (8 + m) * 4 + d];
        }
        sc *= 0.17677669529663687f;          // 32^-0.5
        sc = sc >= 0.0f ? sc : 0.2f * sc;    // LeakyReLU(0.2)
        int ee = e0 + el2;
        if (ee < E) {
            scoresG[ee * 4 + hh] = sc;
            atomicMaxF(&smaxG[dst[ee] * 4 + hh], sc);
        }
    }
}

// ---------------- softmax accumulate ----------------
__global__ void attn_kernel(const int* __restrict__ dst, int E) {
    int idx = blockIdx.x * blockDim.x + threadIdx.x;
    if (idx >= E * 4) return;
    int e = idx >> 2, h = idx & 3;
    int dn = dst[e];
    float ex = expf(scoresG[idx] - smaxG[dn * 4 + h]);
    const float4* vp = (const float4*)(vG + (size_t)e * 32 + h * 8);
    float4 va = vp[0], vb = vp[1];
    float* p = accG + (size_t)dn * 48 + h * 12;
    redAdd4(p,     ex * va.x, ex * va.y, ex * va.z, ex * va.w);
    redAdd4(p + 4, ex * vb.x, ex * vb.y, ex * vb.z, ex * vb.w);
    redAdd4(p + 8, ex, 0.f, 0.f, 0.f);
}

// ---------------- node output ----------------
__global__ void out_kernel(const float* __restrict__ proj_w, float* __restrict__ out, int N) {
    int idx = blockIdx.x * blockDim.x + threadIdx.x;
    if (idx >= N * 4) return;
    int n = idx >> 2, d = idx & 3;
    float den[4];
#pragma unroll
    for (int h = 0; h < 4; h++) den[h] = accG[(size_t)n * 48 + h * 12 + 8];
    float oc[8];
#pragma unroll
    for (int m2 = 0; m2 < 8; m2++) {
        int h = m2 >> 1;
        float dd = den[h];
        float nm = accG[(size_t)n * 48 + h * 12 + (m2 & 1) * 4 + d];
        oc[m2] = dd > 0.0f ? nm / dd : 0.0f;
    }
    int ro = (d == 0) ? 0 : 8;                 // ix2 = [0,1,1,1]
#pragma unroll
    for (int m = 0; m < 8; m++) {
        float r = 0.0f;
#pragma unroll
        for (int m2 = 0; m2 < 8; m2++) r += proj_w[(ro + m) * 8 + m2] * oc[m2];
        out[(size_t)n * 32 + m * 4 + d] = r;
    }
}

// ---------------- launcher ----------------
extern "C" void kernel_launch(void* const* d_in, const int* in_sizes, int n_in,
                              void* d_out, int out_size) {
    const int*   src        = (const int*)d_in[0];
    const int*   dst        = (const int*)d_in[1];
    const float* basis      = (const float*)d_in[2];
    const float* features   = (const float*)d_in[3];
    const float* edge_feats = (const float*)d_in[4];
    const float* w1         = (const float*)d_in[5];
    const float* b1         = (const float*)d_in[6];
    const float* w2         = (const float*)d_in[7];
    const float* b2         = (const float*)d_in[8];
    const float* ln_w       = (const float*)d_in[9];
    const float* ln_b       = (const float*)d_in[10];
    const float* proj_w     = (const float*)d_in[11];
    float* out = (float*)d_out;

    int E = in_sizes[0];
    int N = in_sizes[3] / 32;

    init_kernel<<<(N * 48 + 255) / 256, 256>>>(N);
    prep_w2_kernel<<<96, 256>>>(w2);
    prep_w1_kernel<<<2, 256>>>(w1);
    node_ln_kernel<<<(N + 127) / 128, 128>>>(features, ln_w, ln_b, N);

    size_t smbytes = STOT * sizeof(float);
    cudaFuncSetAttribute(edge_kernel, cudaFuncAttributeMaxDynamicSharedMemorySize, (int)smbytes);
    edge_kernel<<<(E + 63) / 64, 192, smbytes>>>(src, dst, basis, edge_feats, b1, b2, E);

    attn_kernel<<<(E * 4 + 255) / 256, 256>>>(dst, E);
    out_kernel<<<(N * 4 + 255) / 256, 256>>>(proj_w, out, N);
}